// round 5
// baseline (speedup 1.0000x reference)
#include <cuda_runtime.h>
#include <cuda_bf16.h>
#include <math.h>
#include <stdint.h>

#define B_  2
#define S_  2048
#define E_  2048
#define H_  16
#define KV_ 4
#define D_  128
#define WIN_ 1024

// Scratch
__device__ float g_q[(size_t)B_ * S_ * H_ * D_];
__device__ float g_k[(size_t)B_ * S_ * KV_ * D_];
__device__ float g_v[(size_t)B_ * S_ * KV_ * D_];

__device__ __nv_bfloat16 g_xhi[(size_t)B_ * S_ * E_];
__device__ __nv_bfloat16 g_xlo[(size_t)B_ * S_ * E_];
__device__ __nv_bfloat16 g_wqhi[(size_t)H_ * D_ * E_];
__device__ __nv_bfloat16 g_wqlo[(size_t)H_ * D_ * E_];
__device__ __nv_bfloat16 g_wkhi[(size_t)KV_ * D_ * E_];
__device__ __nv_bfloat16 g_wklo[(size_t)KV_ * D_ * E_];
__device__ __nv_bfloat16 g_wvhi[(size_t)KV_ * D_ * E_];
__device__ __nv_bfloat16 g_wvlo[(size_t)KV_ * D_ * E_];
__device__ __nv_bfloat16 g_wohi[(size_t)E_ * H_ * D_];
__device__ __nv_bfloat16 g_wolo[(size_t)E_ * H_ * D_];
__device__ __nv_bfloat16 g_chi[(size_t)B_ * S_ * H_ * D_];
__device__ __nv_bfloat16 g_clo[(size_t)B_ * S_ * H_ * D_];
__device__ __nv_bfloat16 g_qhi[(size_t)B_ * S_ * H_ * D_];
__device__ __nv_bfloat16 g_qlo[(size_t)B_ * S_ * H_ * D_];
__device__ __nv_bfloat16 g_khi[(size_t)B_ * S_ * KV_ * D_];
__device__ __nv_bfloat16 g_klo[(size_t)B_ * S_ * KV_ * D_];
__device__ __nv_bfloat16 g_vhi[(size_t)B_ * S_ * KV_ * D_];
__device__ __nv_bfloat16 g_vlo[(size_t)B_ * S_ * KV_ * D_];

// ---------------------------------------------------------------------------
__global__ __launch_bounds__(256) void split_bf16(
    const float2* __restrict__ x, __nv_bfloat162* __restrict__ hi,
    __nv_bfloat162* __restrict__ lo, int n2)
{
    int i = blockIdx.x * blockDim.x + threadIdx.x;
    if (i >= n2) return;
    float2 v = x[i];
    __nv_bfloat16 h0 = __float2bfloat16(v.x);
    __nv_bfloat16 h1 = __float2bfloat16(v.y);
    __nv_bfloat162 hh; hh.x = h0; hh.y = h1;
    __nv_bfloat162 ll;
    ll.x = __float2bfloat16(v.x - __bfloat162float(h0));
    ll.y = __float2bfloat16(v.y - __bfloat162float(h1));
    hi[i] = hh;
    lo[i] = ll;
}

// ---------------------------------------------------------------------------
// PTX helpers
// ---------------------------------------------------------------------------
#define CP16(dst, src) \
    asm volatile("cp.async.cg.shared.global [%0], [%1], 16;\n" :: "r"(dst), "l"(src))
#define CP_COMMIT() asm volatile("cp.async.commit_group;\n" ::)
#define CP_WAIT2()  asm volatile("cp.async.wait_group 2;\n" ::)
#define CP_WAIT1()  asm volatile("cp.async.wait_group 1;\n" ::)
#define CP_WAIT0()  asm volatile("cp.async.wait_group 0;\n" ::)

#define LDSM4(R, addr) \
    asm volatile("ldmatrix.sync.aligned.m8n8.x4.shared.b16 {%0,%1,%2,%3}, [%4];\n" \
        : "=r"(R[0]), "=r"(R[1]), "=r"(R[2]), "=r"(R[3]) : "r"(addr))
#define LDSM4T(R, addr) \
    asm volatile("ldmatrix.sync.aligned.m8n8.x4.trans.shared.b16 {%0,%1,%2,%3}, [%4];\n" \
        : "=r"(R[0]), "=r"(R[1]), "=r"(R[2]), "=r"(R[3]) : "r"(addr))

#define MMA16816(acc, a, b0, b1) \
    asm volatile("mma.sync.aligned.m16n8k16.row.col.f32.bf16.bf16.f32 " \
        "{%0,%1,%2,%3}, {%4,%5,%6,%7}, {%8,%9}, {%0,%1,%2,%3};\n" \
        : "+f"(acc[0]), "+f"(acc[1]), "+f"(acc[2]), "+f"(acc[3]) \
        : "r"(a[0]), "r"(a[1]), "r"(a[2]), "r"(a[3]), "r"(b0), "r"(b1))

// ---------------------------------------------------------------------------
// mma.sync GEMM core, v2: C[M,N] = Ah@Bh^T + Ah@Bl^T + Al@Bh^T (fp32 accum)
// CTA 128x128, 8 warps (warp tile 64x32), K=32 per stage, 4-stage cp.async.
// Smem stride 80B (granule map 5r mod 32 -> conflict-free). K%32==0, K/32>=3.
// ---------------------------------------------------------------------------
#define GT_TILE  10240u                 // 128 rows * 80 B
#define GT_STAGE (4u * GT_TILE)         // Ah | Al | Bh | Bl = 40960 B
#define GT_SMEM  (4u * GT_STAGE)        // 163840 B

__device__ __forceinline__ void gemm_core(
    const __nv_bfloat16* __restrict__ Ah, const __nv_bfloat16* __restrict__ Al,
    const __nv_bfloat16* __restrict__ Bh, const __nv_bfloat16* __restrict__ Bl,
    float* __restrict__ C, int N, int K, int bm, int bn, char* smem)
{
    const uint32_t sb = (uint32_t)__cvta_generic_to_shared(smem);
    const int tid = threadIdx.x;
    const int lane = tid & 31;
    const int wid = tid >> 5;
    const int wm = wid & 1;
    const int wn = wid >> 1;

    // staging: 2 threads/row, each 2x16B chunks (32 cols per row per stage)
    const int row  = tid >> 1;
    const int hk   = tid & 1;
    const uint32_t so0 = (uint32_t)(row * 80 + hk * 32);
    const size_t aoff = (size_t)(bm * 128 + row) * K + hk * 16;
    const size_t boff = (size_t)(bn * 128 + row) * K + hk * 16;

    auto stage_load = [&](int st, int kt) {
        uint32_t tb = sb + (uint32_t)st * GT_STAGE;
        const __nv_bfloat16* pAh = Ah + aoff + (size_t)kt * 32;
        const __nv_bfloat16* pAl = Al + aoff + (size_t)kt * 32;
        const __nv_bfloat16* pBh = Bh + boff + (size_t)kt * 32;
        const __nv_bfloat16* pBl = Bl + boff + (size_t)kt * 32;
        CP16(tb + so0,                    pAh);
        CP16(tb + so0 + 16,               pAh + 8);
        CP16(tb + GT_TILE + so0,          pAl);
        CP16(tb + GT_TILE + so0 + 16,     pAl + 8);
        CP16(tb + 2 * GT_TILE + so0,      pBh);
        CP16(tb + 2 * GT_TILE + so0 + 16, pBh + 8);
        CP16(tb + 3 * GT_TILE + so0,      pBl);
        CP16(tb + 3 * GT_TILE + so0 + 16, pBl + 8);
        CP_COMMIT();
    };

    // ldmatrix lane bases
    const uint32_t aRow = (uint32_t)((wm * 64 + (lane & 15)) * 80 + (lane >> 4) * 16);
    const uint32_t bRow = (uint32_t)((wn * 32 + ((lane >> 4) << 3) + (lane & 7)) * 80
                                     + ((lane >> 3) & 1) * 16);

    float acc[4][4][4];
    #pragma unroll
    for (int i = 0; i < 4; i++)
        #pragma unroll
        for (int j = 0; j < 4; j++)
            #pragma unroll
            for (int r = 0; r < 4; r++) acc[i][j][r] = 0.f;

    const int T = K / 32;
    stage_load(0, 0);
    stage_load(1, 1);
    stage_load(2, 2);

    for (int t = 0; t < T; t++) {
        CP_WAIT2();
        __syncthreads();
        if (t + 3 < T) stage_load((t + 3) & 3, t + 3);
        else           CP_COMMIT();

        const uint32_t base = sb + (uint32_t)(t & 3) * GT_STAGE;

        // load all fragments for both k16 substeps (max ILP window)
        uint32_t ah[2][4][4], al[2][4][4], bh[2][2][4], bl[2][2][4];
        #pragma unroll
        for (int s = 0; s < 2; s++) {
            #pragma unroll
            for (int mt = 0; mt < 4; mt++) {
                uint32_t ao = base + aRow + mt * (16 * 80) + s * 32;
                LDSM4(ah[s][mt], ao);
                LDSM4(al[s][mt], ao + GT_TILE);
            }
            #pragma unroll
            for (int pr = 0; pr < 2; pr++) {
                uint32_t bo = base + 2 * GT_TILE + bRow + pr * (16 * 80) + s * 32;
                LDSM4(bh[s][pr], bo);
                LDSM4(bl[s][pr], bo + GT_TILE);
            }
        }

        // pass-major issue: 16 independent acc chains between dependent MMAs
        #pragma unroll
        for (int s = 0; s < 2; s++)
            #pragma unroll
            for (int mt = 0; mt < 4; mt++)
                #pragma unroll
                for (int nt = 0; nt < 4; nt++) {
                    const int pr = nt >> 1, q = (nt & 1) * 2;
                    MMA16816(acc[mt][nt], ah[s][mt], bh[s][pr][q], bh[s][pr][q + 1]);
                }
        #pragma unroll
        for (int s = 0; s < 2; s++)
            #pragma unroll
            for (int mt = 0; mt < 4; mt++)
                #pragma unroll
                for (int nt = 0; nt < 4; nt++) {
                    const int pr = nt >> 1, q = (nt & 1) * 2;
                    MMA16816(acc[mt][nt], ah[s][mt], bl[s][pr][q], bl[s][pr][q + 1]);
                }
        #pragma unroll
        for (int s = 0; s < 2; s++)
            #pragma unroll
            for (int mt = 0; mt < 4; mt++)
                #pragma unroll
                for (int nt = 0; nt < 4; nt++) {
                    const int pr = nt >> 1, q = (nt & 1) * 2;
                    MMA16816(acc[mt][nt], al[s][mt], bh[s][pr][q], bh[s][pr][q + 1]);
                }
    }

    // epilogue
    #pragma unroll
    for (int mt = 0; mt < 4; mt++) {
        const int r0 = bm * 128 + wm * 64 + mt * 16 + (lane >> 2);
        #pragma unroll
        for (int nt = 0; nt < 4; nt++) {
            const int c0 = bn * 128 + wn * 32 + nt * 8 + (lane & 3) * 2;
            float2 v0 = make_float2(acc[mt][nt][0], acc[mt][nt][1]);
            float2 v1 = make_float2(acc[mt][nt][2], acc[mt][nt][3]);
            *(float2*)&C[(size_t)r0 * N + c0]       = v0;
            *(float2*)&C[(size_t)(r0 + 8) * N + c0] = v1;
        }
    }
}

// Fused Q/K/V projection: grid.x in [0,24): 0-15 Q tiles, 16-19 K, 20-23 V.
__global__ __launch_bounds__(256, 1) void gemm_qkv(
    const __nv_bfloat16* __restrict__ xh, const __nv_bfloat16* __restrict__ xl,
    const __nv_bfloat16* __restrict__ wqh, const __nv_bfloat16* __restrict__ wql,
    const __nv_bfloat16* __restrict__ wkh, const __nv_bfloat16* __restrict__ wkl,
    const __nv_bfloat16* __restrict__ wvh, const __nv_bfloat16* __restrict__ wvl,
    float* __restrict__ q, float* __restrict__ k, float* __restrict__ v)
{
    extern __shared__ char smem[];
    const int bx = blockIdx.x;
    const __nv_bfloat16 *Bh, *Bl;
    float* C;
    int N, bn;
    if (bx < 16)      { Bh = wqh; Bl = wql; C = q; N = H_ * D_;  bn = bx; }
    else if (bx < 20) { Bh = wkh; Bl = wkl; C = k; N = KV_ * D_; bn = bx - 16; }
    else              { Bh = wvh; Bl = wvl; C = v; N = KV_ * D_; bn = bx - 20; }
    gemm_core(xh, xl, Bh, Bl, C, N, E_, blockIdx.y, bn, smem);
}

__global__ __launch_bounds__(256, 1) void gemm_one(
    const __nv_bfloat16* __restrict__ Ah, const __nv_bfloat16* __restrict__ Al,
    const __nv_bfloat16* __restrict__ Bh, const __nv_bfloat16* __restrict__ Bl,
    float* __restrict__ C, int N, int K)
{
    extern __shared__ char smem[];
    gemm_core(Ah, Al, Bh, Bl, C, N, K, blockIdx.y, blockIdx.x, smem);
}

// ---------------------------------------------------------------------------
// RoPE + RMSNorm -> bf16 hi/lo output. One warp per (row, head).
// ---------------------------------------------------------------------------
__global__ __launch_bounds__(128) void rope_rms_split(
    const float* __restrict__ t, __nv_bfloat16* __restrict__ hi,
    __nv_bfloat16* __restrict__ lo, const float* __restrict__ cs,
    const float* __restrict__ sn, int nheads, int total_warps)
{
    int w = (blockIdx.x * blockDim.x + threadIdx.x) >> 5;
    int lane = threadIdx.x & 31;
    if (w >= total_warps) return;
    int h  = w % nheads;
    int bs = w / nheads;
    int s  = bs % S_;

    size_t base = (size_t)bs * (nheads * D_) + h * D_;
    const float* row = t + base;

    float x1a = row[lane],      x1b = row[lane + 32];
    float x2a = row[lane + 64], x2b = row[lane + 96];
    float ca = cs[s * 64 + lane], cb = cs[s * 64 + lane + 32];
    float sa = sn[s * 64 + lane], sb = sn[s * 64 + lane + 32];

    float o1a =  x1a * ca + x2a * sa;
    float o1b =  x1b * cb + x2b * sb;
    float o2a = -x1a * sa + x2a * ca;
    float o2b = -x1b * sb + x2b * cb;

    float ss = o1a * o1a + o1b * o1b + o2a * o2a + o2b * o2b;
    #pragma unroll
    for (int o = 16; o; o >>= 1) ss += __shfl_xor_sync(0xffffffffu, ss, o);
    float scale = rsqrtf(ss * (1.f / 128.f) + 1.1920928955078125e-07f);

    float v[4] = {o1a * scale, o1b * scale, o2a * scale, o2b * scale};
    int off[4] = {lane, lane + 32, lane + 64, lane + 96};
    #pragma unroll
    for (int u = 0; u < 4; u++) {
        __nv_bfloat16 hh = __float2bfloat16(v[u]);
        hi[base + off[u]] = hh;
        lo[base + off[u]] = __float2bfloat16(v[u] - __bfloat162float(hh));
    }
}

// ---------------------------------------------------------------------------
// Tensor-core sliding-window flash attention (mma.sync, unchanged from R3).
// ---------------------------------------------------------------------------
#define RB 17408   // 64 rows * 272 B (stride 136 bf16)

__global__ __launch_bounds__(256) void attn_mma(
    const __nv_bfloat16* __restrict__ qh, const __nv_bfloat16* __restrict__ ql,
    const __nv_bfloat16* __restrict__ kh, const __nv_bfloat16* __restrict__ kl,
    const __nv_bfloat16* __restrict__ vh, const __nv_bfloat16* __restrict__ vl,
    __nv_bfloat16* __restrict__ chi, __nv_bfloat16* __restrict__ clo)
{
    extern __shared__ char smem[];
    const uint32_t sbase = (uint32_t)__cvta_generic_to_shared(smem);

    const int tid = threadIdx.x, lane = tid & 31, w = tid >> 5;
    const int q0 = blockIdx.x * 128;
    const int h  = blockIdx.y, b = blockIdx.z;
    const int kvh = h >> 2;
    const float scl = 0.08838834764831845f;

    {
        int r = tid >> 1;
        size_t gbase = ((size_t)(b * S_ + q0 + r)) * (H_ * D_) + h * D_;
        const uint4* gh = (const uint4*)(qh + gbase);
        const uint4* gl = (const uint4*)(ql + gbase);
        #pragma unroll
        for (int u = 0; u < 8; u++) {
            int c = (tid & 1) * 8 + u;
            *(uint4*)(smem + (size_t)r * 272 + c * 16)            = gh[c];
            *(uint4*)(smem + 4 * RB + (size_t)r * 272 + c * 16)   = gl[c];
        }
    }
    __syncthreads();

    uint32_t ah[8][4], al[8][4];
    {
        uint32_t qro = (uint32_t)((w * 16 + (lane & 15)) * 272);
        #pragma unroll
        for (int d = 0; d < 8; d++) {
            uint32_t co = (uint32_t)((d * 16 + (lane >> 4) * 8) * 2);
            LDSM4(ah[d], sbase + qro + co);
            LDSM4(al[d], sbase + 4 * RB + qro + co);
        }
    }
    __syncthreads();

    float pacc[16][4];
    #pragma unroll
    for (int g = 0; g < 16; g++)
        #pragma unroll
        for (int r = 0; r < 4; r++) pacc[g][r] = 0.f;

    float m_run0 = -1e30f, m_run1 = -1e30f, l0 = 0.f, l1 = 0.f;

    const int ibase = q0 + w * 16;
    const int i0 = ibase + (lane >> 2);
    const int i1 = i0 + 8;

    int t0 = q0 - 1024; if (t0 < 0) t0 = 0;
    const int n = (q0 + 128 - t0) >> 6;

    const int crow = tid >> 2;
    const size_t grow = ((size_t)b * S_) * (KV_ * D_) + (size_t)kvh * D_;

    {
        size_t gb = grow + (size_t)(t0 + crow) * (KV_ * D_);
        #pragma unroll
        for (int u = 0; u < 4; u++) {
            int c = (tid & 3) * 4 + u;
            uint32_t so = (uint32_t)(crow * 272 + c * 16);
            CP16(sbase + so,          kh + gb + c * 8);
            CP16(sbase + 2 * RB + so, kl + gb + c * 8);
            CP16(sbase + 4 * RB + so, vh + gb + c * 8);
            CP16(sbase + 6 * RB + so, vl + gb + c * 8);
        }
        CP_COMMIT();
    }

    for (int it = 0; it < n; it++) {
        const int t = t0 + it * 64;
        if (it + 1 < n) {
            int st = (it + 1) & 1;
            size_t gb = grow + (size_t)(t + 64 + crow) * (KV_ * D_);
            #pragma unroll
            for (int u = 0; u < 4; u++) {
                int c = (tid & 3) * 4 + u;
                uint32_t so = (uint32_t)(st * RB + crow * 272 + c * 16);
                CP16(sbase + so,          kh + gb + c * 8);
                CP16(sbase + 2 * RB + so, kl + gb + c * 8);
                CP16(sbase + 4 * RB + so, vh + gb + c * 8);
                CP16(sbase + 6 * RB + so, vl + gb + c * 8);
            }
            CP_COMMIT();
            CP_WAIT1();
        } else {
            CP_WAIT0();
        }
        __syncthreads();

        const uint32_t khb = sbase + (it & 1) * RB;
        const uint32_t klb = khb + 2 * RB;
        const uint32_t vhb = khb + 4 * RB;
        const uint32_t vlb = khb + 6 * RB;

        float sacc[8][4];
        #pragma unroll
        for (int g = 0; g < 8; g++)
            #pragma unroll
            for (int r = 0; r < 4; r++) sacc[g][r] = 0.f;

        #pragma unroll
        for (int d = 0; d < 8; d++) {
            uint32_t co = (uint32_t)((d * 16 + ((lane >> 3) & 1) * 8) * 2);
            #pragma unroll
            for (int g = 0; g < 4; g++) {
                uint32_t ro = (uint32_t)((g * 16 + ((lane >> 4) << 3) + (lane & 7)) * 272);
                uint32_t k4h[4], k4l[4];
                LDSM4(k4h, khb + ro + co);
                LDSM4(k4l, klb + ro + co);
                MMA16816(sacc[2 * g],     ah[d], k4h[0], k4h[1]);
                MMA16816(sacc[2 * g],     ah[d], k4l[0], k4l[1]);
                MMA16816(sacc[2 * g],     al[d], k4h[0], k4h[1]);
                MMA16816(sacc[2 * g + 1], ah[d], k4h[2], k4h[3]);
                MMA16816(sacc[2 * g + 1], ah[d], k4l[2], k4l[3]);
                MMA16816(sacc[2 * g + 1], al[d], k4h[2], k4h[3]);
            }
        }

        const bool need_mask = (t + 63 >= ibase) || (t + 1009 <= ibase);
        float m0 = -INFINITY, m1 = -INFINITY;
        #pragma unroll
        for (int g = 0; g < 8; g++) {
            int jb = t + g * 8 + 2 * (lane & 3);
            float s0 = sacc[g][0] * scl, s1 = sacc[g][1] * scl;
            float s2 = sacc[g][2] * scl, s3 = sacc[g][3] * scl;
            if (need_mask) {
                s0 = ((jb     <= i0) && (i0 - jb < 1024))     ? s0 : -INFINITY;
                s1 = ((jb + 1 <= i0) && (i0 - jb - 1 < 1024)) ? s1 : -INFINITY;
                s2 = ((jb     <= i1) && (i1 - jb < 1024))     ? s2 : -INFINITY;
                s3 = ((jb + 1 <= i1) && (i1 - jb - 1 < 1024)) ? s3 : -INFINITY;
            }
            sacc[g][0] = s0; sacc[g][1] = s1; sacc[g][2] = s2; sacc[g][3] = s3;
            m0 = fmaxf(m0, fmaxf(s0, s1));
            m1 = fmaxf(m1, fmaxf(s2, s3));
        }
        m0 = fmaxf(m0, __shfl_xor_sync(0xffffffffu, m0, 1));
        m0 = fmaxf(m0, __shfl_xor_sync(0xffffffffu, m0, 2));
        m1 = fmaxf(m1, __shfl_xor_sync(0xffffffffu, m1, 1));
        m1 = fmaxf(m1, __shfl_xor_sync(0xffffffffu, m1, 2));

        float mn0 = fmaxf(m_run0, m0), mn1 = fmaxf(m_run1, m1);
        float a0 = __expf(m_run0 - mn0), a1 = __expf(m_run1 - mn1);
        m_run0 = mn0; m_run1 = mn1;

        float rs0 = 0.f, rs1 = 0.f;
        #pragma unroll
        for (int g = 0; g < 8; g++) {
            float p0 = __expf(sacc[g][0] - mn0);
            float p1 = __expf(sacc[g][1] - mn0);
            float p2 = __expf(sacc[g][2] - mn1);
            float p3 = __expf(sacc[g][3] - mn1);
            sacc[g][0] = p0; sacc[g][1] = p1; sacc[g][2] = p2; sacc[g][3] = p3;
            rs0 += p0 + p1; rs1 += p2 + p3;
        }
        rs0 += __shfl_xor_sync(0xffffffffu, rs0, 1);
        rs0 += __shfl_xor_sync(0xffffffffu, rs0, 2);
        rs1 += __shfl_xor_sync(0xffffffffu, rs1, 1);
        rs1 += __shfl_xor_sync(0xffffffffu, rs1, 2);
        l0 = l0 * a0 + rs0;
        l1 = l1 * a1 + rs1;

        #pragma unroll
        for (int g = 0; g < 16; g++) {
            pacc[g][0] *= a0; pacc[g][1] *= a0;
            pacc[g][2] *= a1; pacc[g][3] *= a1;
        }

        uint32_t ph[4][4], pl[4][4];
        #pragma unroll
        for (int kt = 0; kt < 4; kt++) {
            #pragma unroll
            for (int qq = 0; qq < 2; qq++) {
                #pragma unroll
                for (int r2 = 0; r2 < 2; r2++) {
                    float x0 = sacc[2 * kt + qq][r2 * 2];
                    float x1 = sacc[2 * kt + qq][r2 * 2 + 1];
                    __nv_bfloat162 hh = __floats2bfloat162_rn(x0, x1);
                    __nv_bfloat162 ll = __floats2bfloat162_rn(
                        x0 - __bfloat162float(hh.x), x1 - __bfloat162float(hh.y));
                    ph[kt][qq * 2 + r2] = *(uint32_t*)&hh;
                    pl[kt][qq * 2 + r2] = *(uint32_t*)&ll;
                }
            }
        }

        #pragma unroll
        for (int kt = 0; kt < 4; kt++) {
            uint32_t ro = (uint32_t)((kt * 16 + (lane & 15)) * 272);
            uint32_t co = (uint32_t)(((lane >> 4) * 8) * 2);
            #pragma unroll
            for (int g = 0; g < 8; g++) {
                uint32_t v4h[4], v4l[4];
                LDSM4T(v4h, vhb + ro + co + g * 32);
                LDSM4T(v4l, vlb + ro + co + g * 32);
                MMA16816(pacc[2 * g],     ph[kt], v4h[0], v4h[1]);
                MMA16816(pacc[2 * g],     pl[kt], v4h[0], v4h[1]);
                MMA16816(pacc[2 * g],     ph[kt], v4l[0], v4l[1]);
                MMA16816(pacc[2 * g + 1], ph[kt], v4h[2], v4h[3]);
                MMA16816(pacc[2 * g + 1], pl[kt], v4h[2], v4h[3]);
                MMA16816(pacc[2 * g + 1], ph[kt], v4l[2], v4l[3]);
            }
        }
        __syncthreads();
    }

    float inv0 = 1.f / l0, inv1 = 1.f / l1;
    size_t base0 = ((size_t)(b * S_ + i0)) * (H_ * D_) + h * D_;
    size_t base1 = base0 + (size_t)8 * (H_ * D_);
    #pragma unroll
    for (int g = 0; g < 16; g++) {
        int col = g * 8 + 2 * (lane & 3);
        float o0 = pacc[g][0] * inv0, o1 = pacc[g][1] * inv0;
        float o2 = pacc[g][2] * inv1, o3 = pacc[g][3] * inv1;
        __nv_bfloat162 h0 = __floats2bfloat162_rn(o0, o1);
        __nv_bfloat162 l0v = __floats2bfloat162_rn(
            o0 - __bfloat162float(h0.x), o1 - __bfloat162float(h0.y));
        __nv_bfloat162 h1 = __floats2bfloat162_rn(o2, o3);
        __nv_bfloat162 l1v = __floats2bfloat162_rn(
            o2 - __bfloat162float(h1.x), o3 - __bfloat162float(h1.y));
        *(uint32_t*)&chi[base0 + col] = *(uint32_t*)&h0;
        *(uint32_t*)&clo[base0 + col] = *(uint32_t*)&l0v;
        *(uint32_t*)&chi[base1 + col] = *(uint32_t*)&h1;
        *(uint32_t*)&clo[base1 + col] = *(uint32_t*)&l1v;
    }
}

// ---------------------------------------------------------------------------
extern "C" void kernel_launch(void* const* d_in, const int* in_sizes, int n_in,
                              void* d_out, int out_size)
{
    const float* x    = (const float*)d_in[0];
    const float* cosp = (const float*)d_in[1];
    const float* sinp = (const float*)d_in[2];
    const float* Wq   = (const float*)d_in[3];
    const float* Wk   = (const float*)d_in[4];
    const float* Wv   = (const float*)d_in[5];
    const float* Wo   = (const float*)d_in[6];
    float* out = (float*)d_out;

    float *qp, *kp, *vp;
    cudaGetSymbolAddress((void**)&qp, g_q);
    cudaGetSymbolAddress((void**)&kp, g_k);
    cudaGetSymbolAddress((void**)&vp, g_v);

    __nv_bfloat16 *xhi, *xlo, *wqhi, *wqlo, *wkhi, *wklo, *wvhi, *wvlo, *wohi, *wolo;
    __nv_bfloat16 *chi, *clo, *qhi, *qlo, *khi, *klo, *vhi, *vlo;
    cudaGetSymbolAddress((void**)&xhi, g_xhi);
    cudaGetSymbolAddress((void**)&xlo, g_xlo);
    cudaGetSymbolAddress((void**)&wqhi, g_wqhi);
    cudaGetSymbolAddress((void**)&wqlo, g_wqlo);
    cudaGetSymbolAddress((void**)&wkhi, g_wkhi);
    cudaGetSymbolAddress((void**)&wklo, g_wklo);
    cudaGetSymbolAddress((void**)&wvhi, g_wvhi);
    cudaGetSymbolAddress((void**)&wvlo, g_wvlo);
    cudaGetSymbolAddress((void**)&wohi, g_wohi);
    cudaGetSymbolAddress((void**)&wolo, g_wolo);
    cudaGetSymbolAddress((void**)&chi, g_chi);
    cudaGetSymbolAddress((void**)&clo, g_clo);
    cudaGetSymbolAddress((void**)&qhi, g_qhi);
    cudaGetSymbolAddress((void**)&qlo, g_qlo);
    cudaGetSymbolAddress((void**)&khi, g_khi);
    cudaGetSymbolAddress((void**)&klo, g_klo);
    cudaGetSymbolAddress((void**)&vhi, g_vhi);
    cudaGetSymbolAddress((void**)&vlo, g_vlo);

    static bool attr_done = false;
    if (!attr_done) {
        cudaFuncSetAttribute(attn_mma,
            cudaFuncAttributeMaxDynamicSharedMemorySize, 8 * RB);
        cudaFuncSetAttribute(gemm_qkv,
            cudaFuncAttributeMaxDynamicSharedMemorySize, GT_SMEM);
        cudaFuncSetAttribute(gemm_one,
            cudaFuncAttributeMaxDynamicSharedMemorySize, GT_SMEM);
        attr_done = true;
    }

    const int M = B_ * S_;

    // splits
    {
        int nx = M * E_ / 2;
        split_bf16<<<(nx + 255) / 256, 256>>>((const float2*)x,
            (__nv_bfloat162*)xhi, (__nv_bfloat162*)xlo, nx);
        int nq = H_ * D_ * E_ / 2;
        split_bf16<<<(nq + 255) / 256, 256>>>((const float2*)Wq,
            (__nv_bfloat162*)wqhi, (__nv_bfloat162*)wqlo, nq);
        int nk = KV_ * D_ * E_ / 2;
        split_bf16<<<(nk + 255) / 256, 256>>>((const float2*)Wk,
            (__nv_bfloat162*)wkhi, (__nv_bfloat162*)wklo, nk);
        split_bf16<<<(nk + 255) / 256, 256>>>((const float2*)Wv,
            (__nv_bfloat162*)wvhi, (__nv_bfloat162*)wvlo, nk);
        int no = E_ * H_ * D_ / 2;
        split_bf16<<<(no + 255) / 256, 256>>>((const float2*)Wo,
            (__nv_bfloat162*)wohi, (__nv_bfloat162*)wolo, no);
    }

    // fused Q/K/V projections
    gemm_qkv<<<dim3(24, M / 128), 256, GT_SMEM>>>(
        xhi, xlo, wqhi, wqlo, wkhi, wklo, wvhi, wvlo, qp, kp, vp);

    // RoPE + RMSNorm -> bf16 hi/lo
    {
        int wq = M * H_;
        int wk = M * KV_;
        rope_rms_split<<<(wq + 3) / 4, 128>>>(qp, qhi, qlo, cosp, sinp, H_, wq);
        rope_rms_split<<<(wk + 3) / 4, 128>>>(kp, khi, klo, cosp, sinp, KV_, wk);
    }

    // V split
    {
        int nv = M * KV_ * D_ / 2;
        split_bf16<<<(nv + 255) / 256, 256>>>((const float2*)vp,
            (__nv_bfloat162*)vhi, (__nv_bfloat162*)vlo, nv);
    }

    // attention
    attn_mma<<<dim3(S_ / 128, H_, B_), 256, 8 * RB>>>(
        qhi, qlo, khi, klo, vhi, vlo, chi, clo);

    // output projection
    gemm_one<<<dim3(E_ / 128, M / 128), 256, GT_SMEM>>>(
        chi, clo, wohi, wolo, out, E_, E_);
}

// round 6
// speedup vs baseline: 1.1296x; 1.1296x over previous
#include <cuda_runtime.h>
#include <cuda_bf16.h>
#include <math.h>
#include <stdint.h>

#define B_  2
#define S_  2048
#define E_  2048
#define H_  16
#define KV_ 4
#define D_  128
#define WIN_ 1024

// Scratch
__device__ float g_q[(size_t)B_ * S_ * H_ * D_];
__device__ float g_k[(size_t)B_ * S_ * KV_ * D_];

__device__ __nv_bfloat16 g_xhi[(size_t)B_ * S_ * E_];
__device__ __nv_bfloat16 g_xlo[(size_t)B_ * S_ * E_];
__device__ __nv_bfloat16 g_wqhi[(size_t)H_ * D_ * E_];
__device__ __nv_bfloat16 g_wqlo[(size_t)H_ * D_ * E_];
__device__ __nv_bfloat16 g_wkhi[(size_t)KV_ * D_ * E_];
__device__ __nv_bfloat16 g_wklo[(size_t)KV_ * D_ * E_];
__device__ __nv_bfloat16 g_wvhi[(size_t)KV_ * D_ * E_];
__device__ __nv_bfloat16 g_wvlo[(size_t)KV_ * D_ * E_];
__device__ __nv_bfloat16 g_wohi[(size_t)E_ * H_ * D_];
__device__ __nv_bfloat16 g_wolo[(size_t)E_ * H_ * D_];
__device__ __nv_bfloat16 g_chi[(size_t)B_ * S_ * H_ * D_];
__device__ __nv_bfloat16 g_clo[(size_t)B_ * S_ * H_ * D_];
__device__ __nv_bfloat16 g_qhi[(size_t)B_ * S_ * H_ * D_];
__device__ __nv_bfloat16 g_qlo[(size_t)B_ * S_ * H_ * D_];
__device__ __nv_bfloat16 g_khi[(size_t)B_ * S_ * KV_ * D_];
__device__ __nv_bfloat16 g_klo[(size_t)B_ * S_ * KV_ * D_];
__device__ __nv_bfloat16 g_vhi[(size_t)B_ * S_ * KV_ * D_];
__device__ __nv_bfloat16 g_vlo[(size_t)B_ * S_ * KV_ * D_];

// ---------------------------------------------------------------------------
__global__ __launch_bounds__(256) void split_bf16(
    const float2* __restrict__ x, __nv_bfloat162* __restrict__ hi,
    __nv_bfloat162* __restrict__ lo, int n2)
{
    int i = blockIdx.x * blockDim.x + threadIdx.x;
    if (i >= n2) return;
    float2 v = x[i];
    __nv_bfloat16 h0 = __float2bfloat16(v.x);
    __nv_bfloat16 h1 = __float2bfloat16(v.y);
    __nv_bfloat162 hh; hh.x = h0; hh.y = h1;
    __nv_bfloat162 ll;
    ll.x = __float2bfloat16(v.x - __bfloat162float(h0));
    ll.y = __float2bfloat16(v.y - __bfloat162float(h1));
    hi[i] = hh;
    lo[i] = ll;
}

// ---------------------------------------------------------------------------
// PTX helpers
// ---------------------------------------------------------------------------
#define CP16(dst, src) \
    asm volatile("cp.async.cg.shared.global [%0], [%1], 16;\n" :: "r"(dst), "l"(src))
#define CP_COMMIT() asm volatile("cp.async.commit_group;\n" ::)
#define CP_WAIT2()  asm volatile("cp.async.wait_group 2;\n" ::)
#define CP_WAIT1()  asm volatile("cp.async.wait_group 1;\n" ::)
#define CP_WAIT0()  asm volatile("cp.async.wait_group 0;\n" ::)

#define LDSM4(R, addr) \
    asm volatile("ldmatrix.sync.aligned.m8n8.x4.shared.b16 {%0,%1,%2,%3}, [%4];\n" \
        : "=r"(R[0]), "=r"(R[1]), "=r"(R[2]), "=r"(R[3]) : "r"(addr))
#define LDSM4T(R, addr) \
    asm volatile("ldmatrix.sync.aligned.m8n8.x4.trans.shared.b16 {%0,%1,%2,%3}, [%4];\n" \
        : "=r"(R[0]), "=r"(R[1]), "=r"(R[2]), "=r"(R[3]) : "r"(addr))

#define MMA16816(acc, a, b0, b1) \
    asm volatile("mma.sync.aligned.m16n8k16.row.col.f32.bf16.bf16.f32 " \
        "{%0,%1,%2,%3}, {%4,%5,%6,%7}, {%8,%9}, {%0,%1,%2,%3};\n" \
        : "+f"(acc[0]), "+f"(acc[1]), "+f"(acc[2]), "+f"(acc[3]) \
        : "r"(a[0]), "r"(a[1]), "r"(a[2]), "r"(a[3]), "r"(b0), "r"(b1))

// ---------------------------------------------------------------------------
// GEMM v3: R3 inner loop, 4-stage pipeline, 1 barrier/K16, 2 CTAs/SM.
//   C = Ah@Bh^T + Ah@Bl^T + Al@Bh^T  (fp32 accum)
// Output: fp32 C, or bf16 hi/lo pair if C == nullptr.
// ---------------------------------------------------------------------------
#define SSTR   24                       // bf16 per smem row (48B, conflict-free)
#define TILE_B (128u * SSTR * 2u)       // 6144 B
#define STG_B  (4u * TILE_B)            // Ah|Al|Bh|Bl = 24576 B
#define G_SMEM (4u * STG_B)             // 98304 B

__device__ __forceinline__ void gemm_core(
    const __nv_bfloat16* __restrict__ Ah, const __nv_bfloat16* __restrict__ Al,
    const __nv_bfloat16* __restrict__ Bh, const __nv_bfloat16* __restrict__ Bl,
    float* __restrict__ C,
    __nv_bfloat16* __restrict__ Chi, __nv_bfloat16* __restrict__ Clo,
    int N, int K, int bm, int bn, char* smem)
{
    const uint32_t sb = (uint32_t)__cvta_generic_to_shared(smem);
    const int tid = threadIdx.x;
    const int lane = tid & 31;
    const int wid = tid >> 5;
    const int wm = wid & 1;
    const int wn = wid >> 1;

    // staging: thread -> (row = tid/2, 8-col chunk = tid&1)
    const int lrow = tid >> 1;
    const int lkc  = tid & 1;
    const __nv_bfloat16* gah = Ah + (size_t)(bm * 128 + lrow) * K + lkc * 8;
    const __nv_bfloat16* gal = Al + (size_t)(bm * 128 + lrow) * K + lkc * 8;
    const __nv_bfloat16* gbh = Bh + (size_t)(bn * 128 + lrow) * K + lkc * 8;
    const __nv_bfloat16* gbl = Bl + (size_t)(bn * 128 + lrow) * K + lkc * 8;
    const uint32_t sOff = (uint32_t)(lrow * SSTR + lkc * 8) * 2;

    // ldmatrix lane offsets (R3-proven)
    const uint32_t aLn = (uint32_t)((wm * 64 + (lane & 15)) * SSTR + (lane >> 4) * 8) * 2;
    const uint32_t bLn = (uint32_t)((wn * 32 + ((lane >> 4) << 3) + (lane & 7)) * SSTR
                                    + ((lane >> 3) & 1) * 8) * 2;

    float acc[4][4][4];
    #pragma unroll
    for (int i = 0; i < 4; i++)
        #pragma unroll
        for (int j = 0; j < 4; j++)
            #pragma unroll
            for (int r = 0; r < 4; r++) acc[i][j][r] = 0.f;

    const int T = K / 16;

    auto stage_load = [&](uint32_t st, int kt) {
        uint32_t base = sb + st * STG_B + sOff;
        CP16(base,              gah + kt * 16);
        CP16(base + TILE_B,     gal + kt * 16);
        CP16(base + 2 * TILE_B, gbh + kt * 16);
        CP16(base + 3 * TILE_B, gbl + kt * 16);
        CP_COMMIT();
    };

    stage_load(0, 0);
    stage_load(1, 1);
    stage_load(2, 2);

    for (int t = 0; t < T; t++) {
        CP_WAIT2();
        __syncthreads();
        if (t + 3 < T) stage_load((uint32_t)((t + 3) & 3), t + 3);
        else           CP_COMMIT();

        const uint32_t ab = sb + (uint32_t)(t & 3) * STG_B;
        const uint32_t bb = ab + 2 * TILE_B;

        uint32_t ah[4][4], al[4][4], bh[2][4], bl[2][4];
        #pragma unroll
        for (int mt = 0; mt < 4; mt++) {
            LDSM4(ah[mt], ab + aLn + mt * (16 * SSTR * 2));
            LDSM4(al[mt], ab + TILE_B + aLn + mt * (16 * SSTR * 2));
        }
        #pragma unroll
        for (int pr = 0; pr < 2; pr++) {
            LDSM4(bh[pr], bb + bLn + pr * (16 * SSTR * 2));
            LDSM4(bl[pr], bb + TILE_B + bLn + pr * (16 * SSTR * 2));
        }

        // pass-major: 16 independent chains between dependent MMAs
        #pragma unroll
        for (int mt = 0; mt < 4; mt++)
            #pragma unroll
            for (int nt = 0; nt < 4; nt++) {
                const int pr = nt >> 1, q = (nt & 1) * 2;
                MMA16816(acc[mt][nt], ah[mt], bh[pr][q], bh[pr][q + 1]);
            }
        #pragma unroll
        for (int mt = 0; mt < 4; mt++)
            #pragma unroll
            for (int nt = 0; nt < 4; nt++) {
                const int pr = nt >> 1, q = (nt & 1) * 2;
                MMA16816(acc[mt][nt], ah[mt], bl[pr][q], bl[pr][q + 1]);
            }
        #pragma unroll
        for (int mt = 0; mt < 4; mt++)
            #pragma unroll
            for (int nt = 0; nt < 4; nt++) {
                const int pr = nt >> 1, q = (nt & 1) * 2;
                MMA16816(acc[mt][nt], al[mt], bh[pr][q], bh[pr][q + 1]);
            }
    }

    // epilogue
    if (C != nullptr) {
        #pragma unroll
        for (int mt = 0; mt < 4; mt++) {
            const int r0 = bm * 128 + wm * 64 + mt * 16 + (lane >> 2);
            #pragma unroll
            for (int nt = 0; nt < 4; nt++) {
                const int c0 = bn * 128 + wn * 32 + nt * 8 + (lane & 3) * 2;
                float2 v0 = make_float2(acc[mt][nt][0], acc[mt][nt][1]);
                float2 v1 = make_float2(acc[mt][nt][2], acc[mt][nt][3]);
                *(float2*)&C[(size_t)r0 * N + c0]       = v0;
                *(float2*)&C[(size_t)(r0 + 8) * N + c0] = v1;
            }
        }
    } else {
        #pragma unroll
        for (int mt = 0; mt < 4; mt++) {
            const int r0 = bm * 128 + wm * 64 + mt * 16 + (lane >> 2);
            #pragma unroll
            for (int nt = 0; nt < 4; nt++) {
                const int c0 = bn * 128 + wn * 32 + nt * 8 + (lane & 3) * 2;
                #pragma unroll
                for (int half = 0; half < 2; half++) {
                    float x0 = acc[mt][nt][half * 2];
                    float x1 = acc[mt][nt][half * 2 + 1];
                    __nv_bfloat162 hh = __floats2bfloat162_rn(x0, x1);
                    __nv_bfloat162 ll = __floats2bfloat162_rn(
                        x0 - __bfloat162float(hh.x), x1 - __bfloat162float(hh.y));
                    size_t off = (size_t)(r0 + half * 8) * N + c0;
                    *(uint32_t*)&Chi[off] = *(uint32_t*)&hh;
                    *(uint32_t*)&Clo[off] = *(uint32_t*)&ll;
                }
            }
        }
    }
}

// Fused Q/K/V projection: grid.x in [0,24): 0-15 Q, 16-19 K, 20-23 V (bf16 out).
__global__ __launch_bounds__(256, 2) void gemm_qkv(
    const __nv_bfloat16* __restrict__ xh, const __nv_bfloat16* __restrict__ xl,
    const __nv_bfloat16* __restrict__ wqh, const __nv_bfloat16* __restrict__ wql,
    const __nv_bfloat16* __restrict__ wkh, const __nv_bfloat16* __restrict__ wkl,
    const __nv_bfloat16* __restrict__ wvh, const __nv_bfloat16* __restrict__ wvl,
    float* __restrict__ q, float* __restrict__ k,
    __nv_bfloat16* __restrict__ vhi, __nv_bfloat16* __restrict__ vlo)
{
    extern __shared__ char smem[];
    const int bx = blockIdx.x;
    if (bx < 16) {
        gemm_core(xh, xl, wqh, wql, q, nullptr, nullptr,
                  H_ * D_, E_, blockIdx.y, bx, smem);
    } else if (bx < 20) {
        gemm_core(xh, xl, wkh, wkl, k, nullptr, nullptr,
                  KV_ * D_, E_, blockIdx.y, bx - 16, smem);
    } else {
        gemm_core(xh, xl, wvh, wvl, nullptr, vhi, vlo,
                  KV_ * D_, E_, blockIdx.y, bx - 20, smem);
    }
}

__global__ __launch_bounds__(256, 2) void gemm_one(
    const __nv_bfloat16* __restrict__ Ah, const __nv_bfloat16* __restrict__ Al,
    const __nv_bfloat16* __restrict__ Bh, const __nv_bfloat16* __restrict__ Bl,
    float* __restrict__ C, int N, int K)
{
    extern __shared__ char smem[];
    gemm_core(Ah, Al, Bh, Bl, C, nullptr, nullptr, N, K,
              blockIdx.y, blockIdx.x, smem);
}

// ---------------------------------------------------------------------------
// RoPE + RMSNorm -> bf16 hi/lo output. One warp per (row, head).
// ---------------------------------------------------------------------------
__global__ __launch_bounds__(128) void rope_rms_split(
    const float* __restrict__ t, __nv_bfloat16* __restrict__ hi,
    __nv_bfloat16* __restrict__ lo, const float* __restrict__ cs,
    const float* __restrict__ sn, int nheads, int total_warps)
{
    int w = (blockIdx.x * blockDim.x + threadIdx.x) >> 5;
    int lane = threadIdx.x & 31;
    if (w >= total_warps) return;
    int h  = w % nheads;
    int bs = w / nheads;
    int s  = bs % S_;

    size_t base = (size_t)bs * (nheads * D_) + h * D_;
    const float* row = t + base;

    float x1a = row[lane],      x1b = row[lane + 32];
    float x2a = row[lane + 64], x2b = row[lane + 96];
    float ca = cs[s * 64 + lane], cb = cs[s * 64 + lane + 32];
    float sa = sn[s * 64 + lane], sb = sn[s * 64 + lane + 32];

    float o1a =  x1a * ca + x2a * sa;
    float o1b =  x1b * cb + x2b * sb;
    float o2a = -x1a * sa + x2a * ca;
    float o2b = -x1b * sb + x2b * cb;

    float ss = o1a * o1a + o1b * o1b + o2a * o2a + o2b * o2b;
    #pragma unroll
    for (int o = 16; o; o >>= 1) ss += __shfl_xor_sync(0xffffffffu, ss, o);
    float scale = rsqrtf(ss * (1.f / 128.f) + 1.1920928955078125e-07f);

    float v[4] = {o1a * scale, o1b * scale, o2a * scale, o2b * scale};
    int off[4] = {lane, lane + 32, lane + 64, lane + 96};
    #pragma unroll
    for (int u = 0; u < 4; u++) {
        __nv_bfloat16 hh = __float2bfloat16(v[u]);
        hi[base + off[u]] = hh;
        lo[base + off[u]] = __float2bfloat16(v[u] - __bfloat162float(hh));
    }
}

// ---------------------------------------------------------------------------
// Tensor-core sliding-window flash attention (mma.sync, unchanged from R3).
// ---------------------------------------------------------------------------
#define RB 17408   // 64 rows * 272 B (stride 136 bf16)

__global__ __launch_bounds__(256) void attn_mma(
    const __nv_bfloat16* __restrict__ qh, const __nv_bfloat16* __restrict__ ql,
    const __nv_bfloat16* __restrict__ kh, const __nv_bfloat16* __restrict__ kl,
    const __nv_bfloat16* __restrict__ vh, const __nv_bfloat16* __restrict__ vl,
    __nv_bfloat16* __restrict__ chi, __nv_bfloat16* __restrict__ clo)
{
    extern __shared__ char smem[];
    const uint32_t sbase = (uint32_t)__cvta_generic_to_shared(smem);

    const int tid = threadIdx.x, lane = tid & 31, w = tid >> 5;
    const int q0 = blockIdx.x * 128;
    const int h  = blockIdx.y, b = blockIdx.z;
    const int kvh = h >> 2;
    const float scl = 0.08838834764831845f;

    {
        int r = tid >> 1;
        size_t gbase = ((size_t)(b * S_ + q0 + r)) * (H_ * D_) + h * D_;
        const uint4* gh = (const uint4*)(qh + gbase);
        const uint4* gl = (const uint4*)(ql + gbase);
        #pragma unroll
        for (int u = 0; u < 8; u++) {
            int c = (tid & 1) * 8 + u;
            *(uint4*)(smem + (size_t)r * 272 + c * 16)            = gh[c];
            *(uint4*)(smem + 4 * RB + (size_t)r * 272 + c * 16)   = gl[c];
        }
    }
    __syncthreads();

    uint32_t ah[8][4], al[8][4];
    {
        uint32_t qro = (uint32_t)((w * 16 + (lane & 15)) * 272);
        #pragma unroll
        for (int d = 0; d < 8; d++) {
            uint32_t co = (uint32_t)((d * 16 + (lane >> 4) * 8) * 2);
            LDSM4(ah[d], sbase + qro + co);
            LDSM4(al[d], sbase + 4 * RB + qro + co);
        }
    }
    __syncthreads();

    float pacc[16][4];
    #pragma unroll
    for (int g = 0; g < 16; g++)
        #pragma unroll
        for (int r = 0; r < 4; r++) pacc[g][r] = 0.f;

    float m_run0 = -1e30f, m_run1 = -1e30f, l0 = 0.f, l1 = 0.f;

    const int ibase = q0 + w * 16;
    const int i0 = ibase + (lane >> 2);
    const int i1 = i0 + 8;

    int t0 = q0 - 1024; if (t0 < 0) t0 = 0;
    const int n = (q0 + 128 - t0) >> 6;

    const int crow = tid >> 2;
    const size_t grow = ((size_t)b * S_) * (KV_ * D_) + (size_t)kvh * D_;

    {
        size_t gb = grow + (size_t)(t0 + crow) * (KV_ * D_);
        #pragma unroll
        for (int u = 0; u < 4; u++) {
            int c = (tid & 3) * 4 + u;
            uint32_t so = (uint32_t)(crow * 272 + c * 16);
            CP16(sbase + so,          kh + gb + c * 8);
            CP16(sbase + 2 * RB + so, kl + gb + c * 8);
            CP16(sbase + 4 * RB + so, vh + gb + c * 8);
            CP16(sbase + 6 * RB + so, vl + gb + c * 8);
        }
        CP_COMMIT();
    }

    for (int it = 0; it < n; it++) {
        const int t = t0 + it * 64;
        if (it + 1 < n) {
            int st = (it + 1) & 1;
            size_t gb = grow + (size_t)(t + 64 + crow) * (KV_ * D_);
            #pragma unroll
            for (int u = 0; u < 4; u++) {
                int c = (tid & 3) * 4 + u;
                uint32_t so = (uint32_t)(st * RB + crow * 272 + c * 16);
                CP16(sbase + so,          kh + gb + c * 8);
                CP16(sbase + 2 * RB + so, kl + gb + c * 8);
                CP16(sbase + 4 * RB + so, vh + gb + c * 8);
                CP16(sbase + 6 * RB + so, vl + gb + c * 8);
            }
            CP_COMMIT();
            CP_WAIT1();
        } else {
            CP_WAIT0();
        }
        __syncthreads();

        const uint32_t khb = sbase + (it & 1) * RB;
        const uint32_t klb = khb + 2 * RB;
        const uint32_t vhb = khb + 4 * RB;
        const uint32_t vlb = khb + 6 * RB;

        float sacc[8][4];
        #pragma unroll
        for (int g = 0; g < 8; g++)
            #pragma unroll
            for (int r = 0; r < 4; r++) sacc[g][r] = 0.f;

        #pragma unroll
        for (int d = 0; d < 8; d++) {
            uint32_t co = (uint32_t)((d * 16 + ((lane >> 3) & 1) * 8) * 2);
            #pragma unroll
            for (int g = 0; g < 4; g++) {
                uint32_t ro = (uint32_t)((g * 16 + ((lane >> 4) << 3) + (lane & 7)) * 272);
                uint32_t k4h[4], k4l[4];
                LDSM4(k4h, khb + ro + co);
                LDSM4(k4l, klb + ro + co);
                MMA16816(sacc[2 * g],     ah[d], k4h[0], k4h[1]);
                MMA16816(sacc[2 * g],     ah[d], k4l[0], k4l[1]);
                MMA16816(sacc[2 * g],     al[d], k4h[0], k4h[1]);
                MMA16816(sacc[2 * g + 1], ah[d], k4h[2], k4h[3]);
                MMA16816(sacc[2 * g + 1], ah[d], k4l[2], k4l[3]);
                MMA16816(sacc[2 * g + 1], al[d], k4h[2], k4h[3]);
            }
        }

        const bool need_mask = (t + 63 >= ibase) || (t + 1009 <= ibase);
        float m0 = -INFINITY, m1 = -INFINITY;
        #pragma unroll
        for (int g = 0; g < 8; g++) {
            int jb = t + g * 8 + 2 * (lane & 3);
            float s0 = sacc[g][0] * scl, s1 = sacc[g][1] * scl;
            float s2 = sacc[g][2] * scl, s3 = sacc[g][3] * scl;
            if (need_mask) {
                s0 = ((jb     <= i0) && (i0 - jb < 1024))     ? s0 : -INFINITY;
                s1 = ((jb + 1 <= i0) && (i0 - jb - 1 < 1024)) ? s1 : -INFINITY;
                s2 = ((jb     <= i1) && (i1 - jb < 1024))     ? s2 : -INFINITY;
                s3 = ((jb + 1 <= i1) && (i1 - jb - 1 < 1024)) ? s3 : -INFINITY;
            }
            sacc[g][0] = s0; sacc[g][1] = s1; sacc[g][2] = s2; sacc[g][3] = s3;
            m0 = fmaxf(m0, fmaxf(s0, s1));
            m1 = fmaxf(m1, fmaxf(s2, s3));
        }
        m0 = fmaxf(m0, __shfl_xor_sync(0xffffffffu, m0, 1));
        m0 = fmaxf(m0, __shfl_xor_sync(0xffffffffu, m0, 2));
        m1 = fmaxf(m1, __shfl_xor_sync(0xffffffffu, m1, 1));
        m1 = fmaxf(m1, __shfl_xor_sync(0xffffffffu, m1, 2));

        float mn0 = fmaxf(m_run0, m0), mn1 = fmaxf(m_run1, m1);
        float a0 = __expf(m_run0 - mn0), a1 = __expf(m_run1 - mn1);
        m_run0 = mn0; m_run1 = mn1;

        float rs0 = 0.f, rs1 = 0.f;
        #pragma unroll
        for (int g = 0; g < 8; g++) {
            float p0 = __expf(sacc[g][0] - mn0);
            float p1 = __expf(sacc[g][1] - mn0);
            float p2 = __expf(sacc[g][2] - mn1);
            float p3 = __expf(sacc[g][3] - mn1);
            sacc[g][0] = p0; sacc[g][1] = p1; sacc[g][2] = p2; sacc[g][3] = p3;
            rs0 += p0 + p1; rs1 += p2 + p3;
        }
        rs0 += __shfl_xor_sync(0xffffffffu, rs0, 1);
        rs0 += __shfl_xor_sync(0xffffffffu, rs0, 2);
        rs1 += __shfl_xor_sync(0xffffffffu, rs1, 1);
        rs1 += __shfl_xor_sync(0xffffffffu, rs1, 2);
        l0 = l0 * a0 + rs0;
        l1 = l1 * a1 + rs1;

        #pragma unroll
        for (int g = 0; g < 16; g++) {
            pacc[g][0] *= a0; pacc[g][1] *= a0;
            pacc[g][2] *= a1; pacc[g][3] *= a1;
        }

        uint32_t ph[4][4], pl[4][4];
        #pragma unroll
        for (int kt = 0; kt < 4; kt++) {
            #pragma unroll
            for (int qq = 0; qq < 2; qq++) {
                #pragma unroll
                for (int r2 = 0; r2 < 2; r2++) {
                    float x0 = sacc[2 * kt + qq][r2 * 2];
                    float x1 = sacc[2 * kt + qq][r2 * 2 + 1];
                    __nv_bfloat162 hh = __floats2bfloat162_rn(x0, x1);
                    __nv_bfloat162 ll = __floats2bfloat162_rn(
                        x0 - __bfloat162float(hh.x), x1 - __bfloat162float(hh.y));
                    ph[kt][qq * 2 + r2] = *(uint32_t*)&hh;
                    pl[kt][qq * 2 + r2] = *(uint32_t*)&ll;
                }
            }
        }

        #pragma unroll
        for (int kt = 0; kt < 4; kt++) {
            uint32_t ro = (uint32_t)((kt * 16 + (lane & 15)) * 272);
            uint32_t co = (uint32_t)(((lane >> 4) * 8) * 2);
            #pragma unroll
            for (int g = 0; g < 8; g++) {
                uint32_t v4h[4], v4l[4];
                LDSM4T(v4h, vhb + ro + co + g * 32);
                LDSM4T(v4l, vlb + ro + co + g * 32);
                MMA16816(pacc[2 * g],     ph[kt], v4h[0], v4h[1]);
                MMA16816(pacc[2 * g],     pl[kt], v4h[0], v4h[1]);
                MMA16816(pacc[2 * g],     ph[kt], v4l[0], v4l[1]);
                MMA16816(pacc[2 * g + 1], ph[kt], v4h[2], v4h[3]);
                MMA16816(pacc[2 * g + 1], pl[kt], v4h[2], v4h[3]);
                MMA16816(pacc[2 * g + 1], ph[kt], v4l[2], v4l[3]);
            }
        }
        __syncthreads();
    }

    float inv0 = 1.f / l0, inv1 = 1.f / l1;
    size_t base0 = ((size_t)(b * S_ + i0)) * (H_ * D_) + h * D_;
    size_t base1 = base0 + (size_t)8 * (H_ * D_);
    #pragma unroll
    for (int g = 0; g < 16; g++) {
        int col = g * 8 + 2 * (lane & 3);
        float o0 = pacc[g][0] * inv0, o1 = pacc[g][1] * inv0;
        float o2 = pacc[g][2] * inv1, o3 = pacc[g][3] * inv1;
        __nv_bfloat162 h0 = __floats2bfloat162_rn(o0, o1);
        __nv_bfloat162 l0v = __floats2bfloat162_rn(
            o0 - __bfloat162float(h0.x), o1 - __bfloat162float(h0.y));
        __nv_bfloat162 h1 = __floats2bfloat162_rn(o2, o3);
        __nv_bfloat162 l1v = __floats2bfloat162_rn(
            o2 - __bfloat162float(h1.x), o3 - __bfloat162float(h1.y));
        *(uint32_t*)&chi[base0 + col] = *(uint32_t*)&h0;
        *(uint32_t*)&clo[base0 + col] = *(uint32_t*)&l0v;
        *(uint32_t*)&chi[base1 + col] = *(uint32_t*)&h1;
        *(uint32_t*)&clo[base1 + col] = *(uint32_t*)&l1v;
    }
}

// ---------------------------------------------------------------------------
extern "C" void kernel_launch(void* const* d_in, const int* in_sizes, int n_in,
                              void* d_out, int out_size)
{
    const float* x    = (const float*)d_in[0];
    const float* cosp = (const float*)d_in[1];
    const float* sinp = (const float*)d_in[2];
    const float* Wq   = (const float*)d_in[3];
    const float* Wk   = (const float*)d_in[4];
    const float* Wv   = (const float*)d_in[5];
    const float* Wo   = (const float*)d_in[6];
    float* out = (float*)d_out;

    float *qp, *kp;
    cudaGetSymbolAddress((void**)&qp, g_q);
    cudaGetSymbolAddress((void**)&kp, g_k);

    __nv_bfloat16 *xhi, *xlo, *wqhi, *wqlo, *wkhi, *wklo, *wvhi, *wvlo, *wohi, *wolo;
    __nv_bfloat16 *chi, *clo, *qhi, *qlo, *khi, *klo, *vhi, *vlo;
    cudaGetSymbolAddress((void**)&xhi, g_xhi);
    cudaGetSymbolAddress((void**)&xlo, g_xlo);
    cudaGetSymbolAddress((void**)&wqhi, g_wqhi);
    cudaGetSymbolAddress((void**)&wqlo, g_wqlo);
    cudaGetSymbolAddress((void**)&wkhi, g_wkhi);
    cudaGetSymbolAddress((void**)&wklo, g_wklo);
    cudaGetSymbolAddress((void**)&wvhi, g_wvhi);
    cudaGetSymbolAddress((void**)&wvlo, g_wvlo);
    cudaGetSymbolAddress((void**)&wohi, g_wohi);
    cudaGetSymbolAddress((void**)&wolo, g_wolo);
    cudaGetSymbolAddress((void**)&chi, g_chi);
    cudaGetSymbolAddress((void**)&clo, g_clo);
    cudaGetSymbolAddress((void**)&qhi, g_qhi);
    cudaGetSymbolAddress((void**)&qlo, g_qlo);
    cudaGetSymbolAddress((void**)&khi, g_khi);
    cudaGetSymbolAddress((void**)&klo, g_klo);
    cudaGetSymbolAddress((void**)&vhi, g_vhi);
    cudaGetSymbolAddress((void**)&vlo, g_vlo);

    static bool attr_done = false;
    if (!attr_done) {
        cudaFuncSetAttribute(attn_mma,
            cudaFuncAttributeMaxDynamicSharedMemorySize, 8 * RB);
        cudaFuncSetAttribute(gemm_qkv,
            cudaFuncAttributeMaxDynamicSharedMemorySize, G_SMEM);
        cudaFuncSetAttribute(gemm_one,
            cudaFuncAttributeMaxDynamicSharedMemorySize, G_SMEM);
        attr_done = true;
    }

    const int M = B_ * S_;

    // splits
    {
        int nx = M * E_ / 2;
        split_bf16<<<(nx + 255) / 256, 256>>>((const float2*)x,
            (__nv_bfloat162*)xhi, (__nv_bfloat162*)xlo, nx);
        int nq = H_ * D_ * E_ / 2;
        split_bf16<<<(nq + 255) / 256, 256>>>((const float2*)Wq,
            (__nv_bfloat162*)wqhi, (__nv_bfloat162*)wqlo, nq);
        int nk = KV_ * D_ * E_ / 2;
        split_bf16<<<(nk + 255) / 256, 256>>>((const float2*)Wk,
            (__nv_bfloat162*)wkhi, (__nv_bfloat162*)wklo, nk);
        split_bf16<<<(nk + 255) / 256, 256>>>((const float2*)Wv,
            (__nv_bfloat162*)wvhi, (__nv_bfloat162*)wvlo, nk);
        int no = E_ * H_ * D_ / 2;
        split_bf16<<<(no + 255) / 256, 256>>>((const float2*)Wo,
            (__nv_bfloat162*)wohi, (__nv_bfloat162*)wolo, no);
    }

    // fused Q/K/V projections (V written directly as bf16 hi/lo)
    gemm_qkv<<<dim3(24, M / 128), 256, G_SMEM>>>(
        xhi, xlo, wqhi, wqlo, wkhi, wklo, wvhi, wvlo, qp, kp, vhi, vlo);

    // RoPE + RMSNorm -> bf16 hi/lo
    {
        int wq = M * H_;
        int wk = M * KV_;
        rope_rms_split<<<(wq + 3) / 4, 128>>>(qp, qhi, qlo, cosp, sinp, H_, wq);
        rope_rms_split<<<(wk + 3) / 4, 128>>>(kp, khi, klo, cosp, sinp, KV_, wk);
    }

    // attention
    attn_mma<<<dim3(S_ / 128, H_, B_), 256, 8 * RB>>>(
        qhi, qlo, khi, klo, vhi, vlo, chi, clo);

    // output projection
    gemm_one<<<dim3(E_ / 128, M / 128), 256, G_SMEM>>>(
        chi, clo, wohi, wolo, out, E_, E_);
}

// round 8
// speedup vs baseline: 1.1513x; 1.0192x over previous
#include <cuda_runtime.h>
#include <cuda_bf16.h>
#include <math.h>
#include <stdint.h>

#define B_  2
#define S_  2048
#define E_  2048
#define H_  16
#define KV_ 4
#define D_  128
#define WIN_ 1024

// bf16 hi/lo scratch
__device__ __nv_bfloat16 g_xhi[(size_t)B_ * S_ * E_];
__device__ __nv_bfloat16 g_xlo[(size_t)B_ * S_ * E_];
__device__ __nv_bfloat16 g_wqhi[(size_t)H_ * D_ * E_];
__device__ __nv_bfloat16 g_wqlo[(size_t)H_ * D_ * E_];
__device__ __nv_bfloat16 g_wkhi[(size_t)KV_ * D_ * E_];
__device__ __nv_bfloat16 g_wklo[(size_t)KV_ * D_ * E_];
__device__ __nv_bfloat16 g_wvhi[(size_t)KV_ * D_ * E_];
__device__ __nv_bfloat16 g_wvlo[(size_t)KV_ * D_ * E_];
__device__ __nv_bfloat16 g_wohi[(size_t)E_ * H_ * D_];
__device__ __nv_bfloat16 g_wolo[(size_t)E_ * H_ * D_];
__device__ __nv_bfloat16 g_chi[(size_t)B_ * S_ * H_ * D_];
__device__ __nv_bfloat16 g_clo[(size_t)B_ * S_ * H_ * D_];
__device__ __nv_bfloat16 g_qhi[(size_t)B_ * S_ * H_ * D_];
__device__ __nv_bfloat16 g_qlo[(size_t)B_ * S_ * H_ * D_];
__device__ __nv_bfloat16 g_khi[(size_t)B_ * S_ * KV_ * D_];
__device__ __nv_bfloat16 g_klo[(size_t)B_ * S_ * KV_ * D_];
__device__ __nv_bfloat16 g_vhi[(size_t)B_ * S_ * KV_ * D_];
__device__ __nv_bfloat16 g_vlo[(size_t)B_ * S_ * KV_ * D_];

// ---------------------------------------------------------------------------
// Fused hi/lo splitter for x, Wq, Wk, Wv, Wo (one launch). float2 units.
// Segments: x (N2_X) | wq (N2_WQ) | wk (N2_WK) | wv (N2_WK) | wo (N2_WQ)
// ---------------------------------------------------------------------------
#define N2_X  ((size_t)B_ * S_ * E_ / 2)        // 4194304
#define N2_WQ ((size_t)H_ * D_ * E_ / 2)        // 2097152
#define N2_WK ((size_t)KV_ * D_ * E_ / 2)       // 524288
#define N2_ALL (N2_X + 2 * N2_WQ + 2 * N2_WK)   // 9437184 (bug fixed)

__global__ __launch_bounds__(256) void split_all(
    const float2* __restrict__ x,  const float2* __restrict__ wq,
    const float2* __restrict__ wk, const float2* __restrict__ wv,
    const float2* __restrict__ wo,
    __nv_bfloat162* __restrict__ xhi,  __nv_bfloat162* __restrict__ xlo,
    __nv_bfloat162* __restrict__ qhi,  __nv_bfloat162* __restrict__ qlo,
    __nv_bfloat162* __restrict__ khi,  __nv_bfloat162* __restrict__ klo,
    __nv_bfloat162* __restrict__ vhi,  __nv_bfloat162* __restrict__ vlo,
    __nv_bfloat162* __restrict__ ohi,  __nv_bfloat162* __restrict__ olo)
{
    size_t i = (size_t)blockIdx.x * blockDim.x + threadIdx.x;
    if (i >= N2_ALL) return;

    const float2* src;
    __nv_bfloat162 *dh, *dl;
    size_t off = i;
    if (off < N2_X)                    { src = x;  dh = xhi; dl = xlo; }
    else if ((off -= N2_X) < N2_WQ)    { src = wq; dh = qhi; dl = qlo; }
    else if ((off -= N2_WQ) < N2_WK)   { src = wk; dh = khi; dl = klo; }
    else if ((off -= N2_WK) < N2_WK)   { src = wv; dh = vhi; dl = vlo; }
    else { off -= N2_WK;                 src = wo; dh = ohi; dl = olo; }

    float2 v = src[off];
    __nv_bfloat16 h0 = __float2bfloat16(v.x);
    __nv_bfloat16 h1 = __float2bfloat16(v.y);
    __nv_bfloat162 hh; hh.x = h0; hh.y = h1;
    __nv_bfloat162 ll;
    ll.x = __float2bfloat16(v.x - __bfloat162float(h0));
    ll.y = __float2bfloat16(v.y - __bfloat162float(h1));
    dh[off] = hh;
    dl[off] = ll;
}

// ---------------------------------------------------------------------------
// PTX helpers
// ---------------------------------------------------------------------------
#define CP16(dst, src) \
    asm volatile("cp.async.cg.shared.global [%0], [%1], 16;\n" :: "r"(dst), "l"(src))
#define CP_COMMIT() asm volatile("cp.async.commit_group;\n" ::)
#define CP_WAIT2()  asm volatile("cp.async.wait_group 2;\n" ::)
#define CP_WAIT1()  asm volatile("cp.async.wait_group 1;\n" ::)
#define CP_WAIT0()  asm volatile("cp.async.wait_group 0;\n" ::)

#define LDSM4(R, addr) \
    asm volatile("ldmatrix.sync.aligned.m8n8.x4.shared.b16 {%0,%1,%2,%3}, [%4];\n" \
        : "=r"(R[0]), "=r"(R[1]), "=r"(R[2]), "=r"(R[3]) : "r"(addr))
#define LDSM4T(R, addr) \
    asm volatile("ldmatrix.sync.aligned.m8n8.x4.trans.shared.b16 {%0,%1,%2,%3}, [%4];\n" \
        : "=r"(R[0]), "=r"(R[1]), "=r"(R[2]), "=r"(R[3]) : "r"(addr))

#define MMA16816(acc, a, b0, b1) \
    asm volatile("mma.sync.aligned.m16n8k16.row.col.f32.bf16.bf16.f32 " \
        "{%0,%1,%2,%3}, {%4,%5,%6,%7}, {%8,%9}, {%0,%1,%2,%3};\n" \
        : "+f"(acc[0]), "+f"(acc[1]), "+f"(acc[2]), "+f"(acc[3]) \
        : "r"(a[0]), "r"(a[1]), "r"(a[2]), "r"(a[3]), "r"(b0), "r"(b1))

// ---------------------------------------------------------------------------
// GEMM core: C = Ah@Bh^T + Ah@Bl^T + Al@Bh^T  (fp32 accum)
// CTA 128x128, 8 warps, 4-stage cp.async pipeline, 1 barrier/K16, 2 CTAs/SM.
// mode 0: fp32 C out. mode 1: bf16 hi/lo out. mode 2: rope+rms -> bf16 hi/lo.
// ---------------------------------------------------------------------------
#define SSTR   24                       // bf16 per smem row (48B, conflict-free)
#define TILE_B (128u * SSTR * 2u)       // 6144 B
#define STG_B  (4u * TILE_B)            // Ah|Al|Bh|Bl = 24576 B
#define G_SMEM (4u * STG_B)             // 98304 B

__device__ __forceinline__ void gemm_core(
    const __nv_bfloat16* __restrict__ Ah, const __nv_bfloat16* __restrict__ Al,
    const __nv_bfloat16* __restrict__ Bh, const __nv_bfloat16* __restrict__ Bl,
    float* __restrict__ C,
    __nv_bfloat16* __restrict__ Chi, __nv_bfloat16* __restrict__ Clo,
    int N, int K, int bm, int bn, char* smem, int mode,
    const float* __restrict__ cs, const float* __restrict__ sn)
{
    const uint32_t sb = (uint32_t)__cvta_generic_to_shared(smem);
    const int tid = threadIdx.x;
    const int lane = tid & 31;
    const int wid = tid >> 5;
    const int wm = wid & 1;
    const int wn = wid >> 1;

    // staging: thread -> (row = tid/2, 8-col chunk = tid&1)
    const int lrow = tid >> 1;
    const int lkc  = tid & 1;
    const __nv_bfloat16* gah = Ah + (size_t)(bm * 128 + lrow) * K + lkc * 8;
    const __nv_bfloat16* gal = Al + (size_t)(bm * 128 + lrow) * K + lkc * 8;
    const __nv_bfloat16* gbh = Bh + (size_t)(bn * 128 + lrow) * K + lkc * 8;
    const __nv_bfloat16* gbl = Bl + (size_t)(bn * 128 + lrow) * K + lkc * 8;
    const uint32_t sOff = (uint32_t)(lrow * SSTR + lkc * 8) * 2;

    const uint32_t aLn = (uint32_t)((wm * 64 + (lane & 15)) * SSTR + (lane >> 4) * 8) * 2;
    const uint32_t bLn = (uint32_t)((wn * 32 + ((lane >> 4) << 3) + (lane & 7)) * SSTR
                                    + ((lane >> 3) & 1) * 8) * 2;

    float acc[4][4][4];
    #pragma unroll
    for (int i = 0; i < 4; i++)
        #pragma unroll
        for (int j = 0; j < 4; j++)
            #pragma unroll
            for (int r = 0; r < 4; r++) acc[i][j][r] = 0.f;

    const int T = K / 16;

    auto stage_load = [&](uint32_t st, int kt) {
        uint32_t base = sb + st * STG_B + sOff;
        CP16(base,              gah + kt * 16);
        CP16(base + TILE_B,     gal + kt * 16);
        CP16(base + 2 * TILE_B, gbh + kt * 16);
        CP16(base + 3 * TILE_B, gbl + kt * 16);
        CP_COMMIT();
    };

    stage_load(0, 0);
    stage_load(1, 1);
    stage_load(2, 2);

    for (int t = 0; t < T; t++) {
        CP_WAIT2();
        __syncthreads();

        const uint32_t ab = sb + (uint32_t)(t & 3) * STG_B;
        const uint32_t bb = ab + 2 * TILE_B;

        // fragments first — let tensor path start ASAP
        uint32_t ah[4][4], al[4][4], bh[2][4], bl[2][4];
        #pragma unroll
        for (int mt = 0; mt < 4; mt++) {
            LDSM4(ah[mt], ab + aLn + mt * (16 * SSTR * 2));
            LDSM4(al[mt], ab + TILE_B + aLn + mt * (16 * SSTR * 2));
        }
        #pragma unroll
        for (int pr = 0; pr < 2; pr++) {
            LDSM4(bh[pr], bb + bLn + pr * (16 * SSTR * 2));
            LDSM4(bl[pr], bb + TILE_B + bLn + pr * (16 * SSTR * 2));
        }

        // prefetch next stage behind the fragment loads
        if (t + 3 < T) stage_load((uint32_t)((t + 3) & 3), t + 3);
        else           CP_COMMIT();

        // pass-major: 16 independent chains between dependent MMAs
        #pragma unroll
        for (int mt = 0; mt < 4; mt++)
            #pragma unroll
            for (int nt = 0; nt < 4; nt++) {
                const int pr = nt >> 1, q = (nt & 1) * 2;
                MMA16816(acc[mt][nt], ah[mt], bh[pr][q], bh[pr][q + 1]);
            }
        #pragma unroll
        for (int mt = 0; mt < 4; mt++)
            #pragma unroll
            for (int nt = 0; nt < 4; nt++) {
                const int pr = nt >> 1, q = (nt & 1) * 2;
                MMA16816(acc[mt][nt], ah[mt], bl[pr][q], bl[pr][q + 1]);
            }
        #pragma unroll
        for (int mt = 0; mt < 4; mt++)
            #pragma unroll
            for (int nt = 0; nt < 4; nt++) {
                const int pr = nt >> 1, q = (nt & 1) * 2;
                MMA16816(acc[mt][nt], al[mt], bh[pr][q], bh[pr][q + 1]);
            }
    }

    if (mode == 0) {
        #pragma unroll
        for (int mt = 0; mt < 4; mt++) {
            const int r0 = bm * 128 + wm * 64 + mt * 16 + (lane >> 2);
            #pragma unroll
            for (int nt = 0; nt < 4; nt++) {
                const int c0 = bn * 128 + wn * 32 + nt * 8 + (lane & 3) * 2;
                *(float2*)&C[(size_t)r0 * N + c0] =
                    make_float2(acc[mt][nt][0], acc[mt][nt][1]);
                *(float2*)&C[(size_t)(r0 + 8) * N + c0] =
                    make_float2(acc[mt][nt][2], acc[mt][nt][3]);
            }
        }
    } else if (mode == 1) {
        #pragma unroll
        for (int mt = 0; mt < 4; mt++) {
            const int r0 = bm * 128 + wm * 64 + mt * 16 + (lane >> 2);
            #pragma unroll
            for (int nt = 0; nt < 4; nt++) {
                const int c0 = bn * 128 + wn * 32 + nt * 8 + (lane & 3) * 2;
                #pragma unroll
                for (int half = 0; half < 2; half++) {
                    float x0 = acc[mt][nt][half * 2];
                    float x1 = acc[mt][nt][half * 2 + 1];
                    __nv_bfloat162 hh = __floats2bfloat162_rn(x0, x1);
                    __nv_bfloat162 ll = __floats2bfloat162_rn(
                        x0 - __bfloat162float(hh.x), x1 - __bfloat162float(hh.y));
                    size_t off = (size_t)(r0 + half * 8) * N + c0;
                    *(uint32_t*)&Chi[off] = *(uint32_t*)&hh;
                    *(uint32_t*)&Clo[off] = *(uint32_t*)&ll;
                }
            }
        }
    } else {
        // mode 2: rope + rmsnorm fused epilogue (tile = 128 tokens x 1 head)
        CP_WAIT0();
        __syncthreads();
        float* st = (float*)smem;               // 128 x 132 fp32 (67.6 KB)
        #pragma unroll
        for (int mt = 0; mt < 4; mt++) {
            const int r0 = wm * 64 + mt * 16 + (lane >> 2);
            #pragma unroll
            for (int nt = 0; nt < 4; nt++) {
                const int c0 = wn * 32 + nt * 8 + (lane & 3) * 2;
                *(float2*)&st[r0 * 132 + c0] =
                    make_float2(acc[mt][nt][0], acc[mt][nt][1]);
                *(float2*)&st[(r0 + 8) * 132 + c0] =
                    make_float2(acc[mt][nt][2], acc[mt][nt][3]);
            }
        }
        __syncthreads();

        const int cb = bn * 128;
        for (int rr = 0; rr < 16; rr++) {
            int r = wid * 16 + rr;
            int grow_ = bm * 128 + r;
            int s = grow_ & (S_ - 1);
            float x1a = st[r * 132 + lane],      x1b = st[r * 132 + lane + 32];
            float x2a = st[r * 132 + lane + 64], x2b = st[r * 132 + lane + 96];
            float ca = cs[s * 64 + lane], cbv = cs[s * 64 + lane + 32];
            float sa = sn[s * 64 + lane], sbv = sn[s * 64 + lane + 32];

            float o1a =  x1a * ca  + x2a * sa;
            float o1b =  x1b * cbv + x2b * sbv;
            float o2a = -x1a * sa  + x2a * ca;
            float o2b = -x1b * sbv + x2b * cbv;

            float ss = o1a * o1a + o1b * o1b + o2a * o2a + o2b * o2b;
            #pragma unroll
            for (int o = 16; o; o >>= 1) ss += __shfl_xor_sync(0xffffffffu, ss, o);
            float scale = rsqrtf(ss * (1.f / 128.f) + 1.1920928955078125e-07f);

            float v4[4] = {o1a * scale, o1b * scale, o2a * scale, o2b * scale};
            size_t gb = (size_t)grow_ * N + cb + lane;
            #pragma unroll
            for (int u = 0; u < 4; u++) {
                __nv_bfloat16 hh = __float2bfloat16(v4[u]);
                Chi[gb + u * 32] = hh;
                Clo[gb + u * 32] = __float2bfloat16(v4[u] - __bfloat162float(hh));
            }
        }
    }
}

// Fused Q/K/V projection + rope/rms epilogue for Q,K; bf16 split for V.
__global__ __launch_bounds__(256, 2) void gemm_qkv(
    const __nv_bfloat16* __restrict__ xh, const __nv_bfloat16* __restrict__ xl,
    const __nv_bfloat16* __restrict__ wqh, const __nv_bfloat16* __restrict__ wql,
    const __nv_bfloat16* __restrict__ wkh, const __nv_bfloat16* __restrict__ wkl,
    const __nv_bfloat16* __restrict__ wvh, const __nv_bfloat16* __restrict__ wvl,
    __nv_bfloat16* __restrict__ qhi, __nv_bfloat16* __restrict__ qlo,
    __nv_bfloat16* __restrict__ khi, __nv_bfloat16* __restrict__ klo,
    __nv_bfloat16* __restrict__ vhi, __nv_bfloat16* __restrict__ vlo,
    const float* __restrict__ cosp, const float* __restrict__ sinp)
{
    extern __shared__ char smem[];
    const int bx = blockIdx.x;
    if (bx < 16) {
        gemm_core(xh, xl, wqh, wql, nullptr, qhi, qlo,
                  H_ * D_, E_, blockIdx.y, bx, smem, 2, cosp, sinp);
    } else if (bx < 20) {
        gemm_core(xh, xl, wkh, wkl, nullptr, khi, klo,
                  KV_ * D_, E_, blockIdx.y, bx - 16, smem, 2, cosp, sinp);
    } else {
        gemm_core(xh, xl, wvh, wvl, nullptr, vhi, vlo,
                  KV_ * D_, E_, blockIdx.y, bx - 20, smem, 1, nullptr, nullptr);
    }
}

__global__ __launch_bounds__(256, 2) void gemm_one(
    const __nv_bfloat16* __restrict__ Ah, const __nv_bfloat16* __restrict__ Al,
    const __nv_bfloat16* __restrict__ Bh, const __nv_bfloat16* __restrict__ Bl,
    float* __restrict__ C, int N, int K)
{
    extern __shared__ char smem[];
    gemm_core(Ah, Al, Bh, Bl, C, nullptr, nullptr, N, K,
              blockIdx.y, blockIdx.x, smem, 0, nullptr, nullptr);
}

// ---------------------------------------------------------------------------
// Tensor-core sliding-window flash attention (mma.sync, unchanged from R3).
// ---------------------------------------------------------------------------
#define RB 17408   // 64 rows * 272 B (stride 136 bf16)

__global__ __launch_bounds__(256) void attn_mma(
    const __nv_bfloat16* __restrict__ qh, const __nv_bfloat16* __restrict__ ql,
    const __nv_bfloat16* __restrict__ kh, const __nv_bfloat16* __restrict__ kl,
    const __nv_bfloat16* __restrict__ vh, const __nv_bfloat16* __restrict__ vl,
    __nv_bfloat16* __restrict__ chi, __nv_bfloat16* __restrict__ clo)
{
    extern __shared__ char smem[];
    const uint32_t sbase = (uint32_t)__cvta_generic_to_shared(smem);

    const int tid = threadIdx.x, lane = tid & 31, w = tid >> 5;
    const int q0 = blockIdx.x * 128;
    const int h  = blockIdx.y, b = blockIdx.z;
    const int kvh = h >> 2;
    const float scl = 0.08838834764831845f;

    {
        int r = tid >> 1;
        size_t gbase = ((size_t)(b * S_ + q0 + r)) * (H_ * D_) + h * D_;
        const uint4* gh = (const uint4*)(qh + gbase);
        const uint4* gl = (const uint4*)(ql + gbase);
        #pragma unroll
        for (int u = 0; u < 8; u++) {
            int c = (tid & 1) * 8 + u;
            *(uint4*)(smem + (size_t)r * 272 + c * 16)            = gh[c];
            *(uint4*)(smem + 4 * RB + (size_t)r * 272 + c * 16)   = gl[c];
        }
    }
    __syncthreads();

    uint32_t ah[8][4], al[8][4];
    {
        uint32_t qro = (uint32_t)((w * 16 + (lane & 15)) * 272);
        #pragma unroll
        for (int d = 0; d < 8; d++) {
            uint32_t co = (uint32_t)((d * 16 + (lane >> 4) * 8) * 2);
            LDSM4(ah[d], sbase + qro + co);
            LDSM4(al[d], sbase + 4 * RB + qro + co);
        }
    }
    __syncthreads();

    float pacc[16][4];
    #pragma unroll
    for (int g = 0; g < 16; g++)
        #pragma unroll
        for (int r = 0; r < 4; r++) pacc[g][r] = 0.f;

    float m_run0 = -1e30f, m_run1 = -1e30f, l0 = 0.f, l1 = 0.f;

    const int ibase = q0 + w * 16;
    const int i0 = ibase + (lane >> 2);
    const int i1 = i0 + 8;

    int t0 = q0 - 1024; if (t0 < 0) t0 = 0;
    const int n = (q0 + 128 - t0) >> 6;

    const int crow = tid >> 2;
    const size_t grow = ((size_t)b * S_) * (KV_ * D_) + (size_t)kvh * D_;

    {
        size_t gb = grow + (size_t)(t0 + crow) * (KV_ * D_);
        #pragma unroll
        for (int u = 0; u < 4; u++) {
            int c = (tid & 3) * 4 + u;
            uint32_t so = (uint32_t)(crow * 272 + c * 16);
            CP16(sbase + so,          kh + gb + c * 8);
            CP16(sbase + 2 * RB + so, kl + gb + c * 8);
            CP16(sbase + 4 * RB + so, vh + gb + c * 8);
            CP16(sbase + 6 * RB + so, vl + gb + c * 8);
        }
        CP_COMMIT();
    }

    for (int it = 0; it < n; it++) {
        const int t = t0 + it * 64;
        if (it + 1 < n) {
            int st = (it + 1) & 1;
            size_t gb = grow + (size_t)(t + 64 + crow) * (KV_ * D_);
            #pragma unroll
            for (int u = 0; u < 4; u++) {
                int c = (tid & 3) * 4 + u;
                uint32_t so = (uint32_t)(st * RB + crow * 272 + c * 16);
                CP16(sbase + so,          kh + gb + c * 8);
                CP16(sbase + 2 * RB + so, kl + gb + c * 8);
                CP16(sbase + 4 * RB + so, vh + gb + c * 8);
                CP16(sbase + 6 * RB + so, vl + gb + c * 8);
            }
            CP_COMMIT();
            CP_WAIT1();
        } else {
            CP_WAIT0();
        }
        __syncthreads();

        const uint32_t khb = sbase + (it & 1) * RB;
        const uint32_t klb = khb + 2 * RB;
        const uint32_t vhb = khb + 4 * RB;
        const uint32_t vlb = khb + 6 * RB;

        float sacc[8][4];
        #pragma unroll
        for (int g = 0; g < 8; g++)
            #pragma unroll
            for (int r = 0; r < 4; r++) sacc[g][r] = 0.f;

        #pragma unroll
        for (int d = 0; d < 8; d++) {
            uint32_t co = (uint32_t)((d * 16 + ((lane >> 3) & 1) * 8) * 2);
            #pragma unroll
            for (int g = 0; g < 4; g++) {
                uint32_t ro = (uint32_t)((g * 16 + ((lane >> 4) << 3) + (lane & 7)) * 272);
                uint32_t k4h[4], k4l[4];
                LDSM4(k4h, khb + ro + co);
                LDSM4(k4l, klb + ro + co);
                MMA16816(sacc[2 * g],     ah[d], k4h[0], k4h[1]);
                MMA16816(sacc[2 * g],     ah[d], k4l[0], k4l[1]);
                MMA16816(sacc[2 * g],     al[d], k4h[0], k4h[1]);
                MMA16816(sacc[2 * g + 1], ah[d], k4h[2], k4h[3]);
                MMA16816(sacc[2 * g + 1], ah[d], k4l[2], k4l[3]);
                MMA16816(sacc[2 * g + 1], al[d], k4h[2], k4h[3]);
            }
        }

        const bool need_mask = (t + 63 >= ibase) || (t + 1009 <= ibase);
        float m0 = -INFINITY, m1 = -INFINITY;
        #pragma unroll
        for (int g = 0; g < 8; g++) {
            int jb = t + g * 8 + 2 * (lane & 3);
            float s0 = sacc[g][0] * scl, s1 = sacc[g][1] * scl;
            float s2 = sacc[g][2] * scl, s3 = sacc[g][3] * scl;
            if (need_mask) {
                s0 = ((jb     <= i0) && (i0 - jb < 1024))     ? s0 : -INFINITY;
                s1 = ((jb + 1 <= i0) && (i0 - jb - 1 < 1024)) ? s1 : -INFINITY;
                s2 = ((jb     <= i1) && (i1 - jb < 1024))     ? s2 : -INFINITY;
                s3 = ((jb + 1 <= i1) && (i1 - jb - 1 < 1024)) ? s3 : -INFINITY;
            }
            sacc[g][0] = s0; sacc[g][1] = s1; sacc[g][2] = s2; sacc[g][3] = s3;
            m0 = fmaxf(m0, fmaxf(s0, s1));
            m1 = fmaxf(m1, fmaxf(s2, s3));
        }
        m0 = fmaxf(m0, __shfl_xor_sync(0xffffffffu, m0, 1));
        m0 = fmaxf(m0, __shfl_xor_sync(0xffffffffu, m0, 2));
        m1 = fmaxf(m1, __shfl_xor_sync(0xffffffffu, m1, 1));
        m1 = fmaxf(m1, __shfl_xor_sync(0xffffffffu, m1, 2));

        float mn0 = fmaxf(m_run0, m0), mn1 = fmaxf(m_run1, m1);
        float a0 = __expf(m_run0 - mn0), a1 = __expf(m_run1 - mn1);
        m_run0 = mn0; m_run1 = mn1;

        float rs0 = 0.f, rs1 = 0.f;
        #pragma unroll
        for (int g = 0; g < 8; g++) {
            float p0 = __expf(sacc[g][0] - mn0);
            float p1 = __expf(sacc[g][1] - mn0);
            float p2 = __expf(sacc[g][2] - mn1);
            float p3 = __expf(sacc[g][3] - mn1);
            sacc[g][0] = p0; sacc[g][1] = p1; sacc[g][2] = p2; sacc[g][3] = p3;
            rs0 += p0 + p1; rs1 += p2 + p3;
        }
        rs0 += __shfl_xor_sync(0xffffffffu, rs0, 1);
        rs0 += __shfl_xor_sync(0xffffffffu, rs0, 2);
        rs1 += __shfl_xor_sync(0xffffffffu, rs1, 1);
        rs1 += __shfl_xor_sync(0xffffffffu, rs1, 2);
        l0 = l0 * a0 + rs0;
        l1 = l1 * a1 + rs1;

        #pragma unroll
        for (int g = 0; g < 16; g++) {
            pacc[g][0] *= a0; pacc[g][1] *= a0;
            pacc[g][2] *= a1; pacc[g][3] *= a1;
        }

        uint32_t ph[4][4], pl[4][4];
        #pragma unroll
        for (int kt = 0; kt < 4; kt++) {
            #pragma unroll
            for (int qq = 0; qq < 2; qq++) {
                #pragma unroll
                for (int r2 = 0; r2 < 2; r2++) {
                    float x0 = sacc[2 * kt + qq][r2 * 2];
                    float x1 = sacc[2 * kt + qq][r2 * 2 + 1];
                    __nv_bfloat162 hh = __floats2bfloat162_rn(x0, x1);
                    __nv_bfloat162 ll = __floats2bfloat162_rn(
                        x0 - __bfloat162float(hh.x), x1 - __bfloat162float(hh.y));
                    ph[kt][qq * 2 + r2] = *(uint32_t*)&hh;
                    pl[kt][qq * 2 + r2] = *(uint32_t*)&ll;
                }
            }
        }

        #pragma unroll
        for (int kt = 0; kt < 4; kt++) {
            uint32_t ro = (uint32_t)((kt * 16 + (lane & 15)) * 272);
            uint32_t co = (uint32_t)(((lane >> 4) * 8) * 2);
            #pragma unroll
            for (int g = 0; g < 8; g++) {
                uint32_t v4h[4], v4l[4];
                LDSM4T(v4h, vhb + ro + co + g * 32);
                LDSM4T(v4l, vlb + ro + co + g * 32);
                MMA16816(pacc[2 * g],     ph[kt], v4h[0], v4h[1]);
                MMA16816(pacc[2 * g],     pl[kt], v4h[0], v4h[1]);
                MMA16816(pacc[2 * g],     ph[kt], v4l[0], v4l[1]);
                MMA16816(pacc[2 * g + 1], ph[kt], v4h[2], v4h[3]);
                MMA16816(pacc[2 * g + 1], pl[kt], v4h[2], v4h[3]);
                MMA16816(pacc[2 * g + 1], ph[kt], v4l[2], v4l[3]);
            }
        }
        __syncthreads();
    }

    float inv0 = 1.f / l0, inv1 = 1.f / l1;
    size_t base0 = ((size_t)(b * S_ + i0)) * (H_ * D_) + h * D_;
    size_t base1 = base0 + (size_t)8 * (H_ * D_);
    #pragma unroll
    for (int g = 0; g < 16; g++) {
        int col = g * 8 + 2 * (lane & 3);
        float o0 = pacc[g][0] * inv0, o1 = pacc[g][1] * inv0;
        float o2 = pacc[g][2] * inv1, o3 = pacc[g][3] * inv1;
        __nv_bfloat162 h0 = __floats2bfloat162_rn(o0, o1);
        __nv_bfloat162 l0v = __floats2bfloat162_rn(
            o0 - __bfloat162float(h0.x), o1 - __bfloat162float(h0.y));
        __nv_bfloat162 h1 = __floats2bfloat162_rn(o2, o3);
        __nv_bfloat162 l1v = __floats2bfloat162_rn(
            o2 - __bfloat162float(h1.x), o3 - __bfloat162float(h1.y));
        *(uint32_t*)&chi[base0 + col] = *(uint32_t*)&h0;
        *(uint32_t*)&clo[base0 + col] = *(uint32_t*)&l0v;
        *(uint32_t*)&chi[base1 + col] = *(uint32_t*)&h1;
        *(uint32_t*)&clo[base1 + col] = *(uint32_t*)&l1v;
    }
}

// ---------------------------------------------------------------------------
extern "C" void kernel_launch(void* const* d_in, const int* in_sizes, int n_in,
                              void* d_out, int out_size)
{
    const float* x    = (const float*)d_in[0];
    const float* cosp = (const float*)d_in[1];
    const float* sinp = (const float*)d_in[2];
    const float* Wq   = (const float*)d_in[3];
    const float* Wk   = (const float*)d_in[4];
    const float* Wv   = (const float*)d_in[5];
    const float* Wo   = (const float*)d_in[6];
    float* out = (float*)d_out;

    __nv_bfloat16 *xhi, *xlo, *wqhi, *wqlo, *wkhi, *wklo, *wvhi, *wvlo, *wohi, *wolo;
    __nv_bfloat16 *chi, *clo, *qhi, *qlo, *khi, *klo, *vhi, *vlo;
    cudaGetSymbolAddress((void**)&xhi, g_xhi);
    cudaGetSymbolAddress((void**)&xlo, g_xlo);
    cudaGetSymbolAddress((void**)&wqhi, g_wqhi);
    cudaGetSymbolAddress((void**)&wqlo, g_wqlo);
    cudaGetSymbolAddress((void**)&wkhi, g_wkhi);
    cudaGetSymbolAddress((void**)&wklo, g_wklo);
    cudaGetSymbolAddress((void**)&wvhi, g_wvhi);
    cudaGetSymbolAddress((void**)&wvlo, g_wvlo);
    cudaGetSymbolAddress((void**)&wohi, g_wohi);
    cudaGetSymbolAddress((void**)&wolo, g_wolo);
    cudaGetSymbolAddress((void**)&chi, g_chi);
    cudaGetSymbolAddress((void**)&clo, g_clo);
    cudaGetSymbolAddress((void**)&qhi, g_qhi);
    cudaGetSymbolAddress((void**)&qlo, g_qlo);
    cudaGetSymbolAddress((void**)&khi, g_khi);
    cudaGetSymbolAddress((void**)&klo, g_klo);
    cudaGetSymbolAddress((void**)&vhi, g_vhi);
    cudaGetSymbolAddress((void**)&vlo, g_vlo);

    static bool attr_done = false;
    if (!attr_done) {
        cudaFuncSetAttribute(attn_mma,
            cudaFuncAttributeMaxDynamicSharedMemorySize, 8 * RB);
        cudaFuncSetAttribute(gemm_qkv,
            cudaFuncAttributeMaxDynamicSharedMemorySize, G_SMEM);
        cudaFuncSetAttribute(gemm_one,
            cudaFuncAttributeMaxDynamicSharedMemorySize, G_SMEM);
        attr_done = true;
    }

    const int M = B_ * S_;

    // one fused split launch
    {
        size_t blocks = (N2_ALL + 255) / 256;
        split_all<<<(unsigned)blocks, 256>>>(
            (const float2*)x, (const float2*)Wq, (const float2*)Wk,
            (const float2*)Wv, (const float2*)Wo,
            (__nv_bfloat162*)xhi,  (__nv_bfloat162*)xlo,
            (__nv_bfloat162*)wqhi, (__nv_bfloat162*)wqlo,
            (__nv_bfloat162*)wkhi, (__nv_bfloat162*)wklo,
            (__nv_bfloat162*)wvhi, (__nv_bfloat162*)wvlo,
            (__nv_bfloat162*)wohi, (__nv_bfloat162*)wolo);
    }

    // fused Q/K/V projections + rope/rms epilogue (Q,K) + bf16 split (V)
    gemm_qkv<<<dim3(24, M / 128), 256, G_SMEM>>>(
        xhi, xlo, wqhi, wqlo, wkhi, wklo, wvhi, wvlo,
        qhi, qlo, khi, klo, vhi, vlo, cosp, sinp);

    // attention
    attn_mma<<<dim3(S_ / 128, H_, B_), 256, 8 * RB>>>(
        qhi, qlo, khi, klo, vhi, vlo, chi, clo);

    // output projection
    gemm_one<<<dim3(E_ / 128, M / 128), 256, G_SMEM>>>(
        chi, clo, wohi, wolo, out, E_, E_);
}

// round 9
// speedup vs baseline: 1.5997x; 1.3894x over previous
#include <cuda_runtime.h>
#include <cuda_bf16.h>
#include <cuda_fp16.h>
#include <math.h>
#include <stdint.h>

#define B_  2
#define S_  2048
#define E_  2048
#define H_  16
#define KV_ 4
#define D_  128
#define WIN_ 1024

// fp16 hi/lo scratch (GEMM operands)
__device__ __half g_xhi[(size_t)B_ * S_ * E_];
__device__ __half g_xlo[(size_t)B_ * S_ * E_];
__device__ __half g_wqhi[(size_t)H_ * D_ * E_];
__device__ __half g_wqlo[(size_t)H_ * D_ * E_];
__device__ __half g_wkhi[(size_t)KV_ * D_ * E_];
__device__ __half g_wklo[(size_t)KV_ * D_ * E_];
__device__ __half g_wvhi[(size_t)KV_ * D_ * E_];
__device__ __half g_wvlo[(size_t)KV_ * D_ * E_];
__device__ __half g_wohi[(size_t)E_ * H_ * D_];
__device__ __half g_wolo[(size_t)E_ * H_ * D_];
__device__ __half g_chi[(size_t)B_ * S_ * H_ * D_];
__device__ __half g_clo[(size_t)B_ * S_ * H_ * D_];

// bf16 hi/lo scratch (attention operands, 3-pass compensated)
__device__ __nv_bfloat16 g_qhi[(size_t)B_ * S_ * H_ * D_];
__device__ __nv_bfloat16 g_qlo[(size_t)B_ * S_ * H_ * D_];
__device__ __nv_bfloat16 g_khi[(size_t)B_ * S_ * KV_ * D_];
__device__ __nv_bfloat16 g_klo[(size_t)B_ * S_ * KV_ * D_];
__device__ __nv_bfloat16 g_vhi[(size_t)B_ * S_ * KV_ * D_];
__device__ __nv_bfloat16 g_vlo[(size_t)B_ * S_ * KV_ * D_];

// ---------------------------------------------------------------------------
// Fused fp16 hi/lo splitter for x, Wq, Wk, Wv, Wo (one launch). float2 units.
// ---------------------------------------------------------------------------
#define N2_X  ((size_t)B_ * S_ * E_ / 2)
#define N2_WQ ((size_t)H_ * D_ * E_ / 2)
#define N2_WK ((size_t)KV_ * D_ * E_ / 2)
#define N2_ALL (N2_X + 2 * N2_WQ + 2 * N2_WK)

__global__ __launch_bounds__(256) void split_all(
    const float2* __restrict__ x,  const float2* __restrict__ wq,
    const float2* __restrict__ wk, const float2* __restrict__ wv,
    const float2* __restrict__ wo,
    __half2* __restrict__ xhi,  __half2* __restrict__ xlo,
    __half2* __restrict__ qhi,  __half2* __restrict__ qlo,
    __half2* __restrict__ khi,  __half2* __restrict__ klo,
    __half2* __restrict__ vhi,  __half2* __restrict__ vlo,
    __half2* __restrict__ ohi,  __half2* __restrict__ olo)
{
    size_t i = (size_t)blockIdx.x * blockDim.x + threadIdx.x;
    if (i >= N2_ALL) return;

    const float2* src;
    __half2 *dh, *dl;
    size_t off = i;
    if (off < N2_X)                    { src = x;  dh = xhi; dl = xlo; }
    else if ((off -= N2_X) < N2_WQ)    { src = wq; dh = qhi; dl = qlo; }
    else if ((off -= N2_WQ) < N2_WK)   { src = wk; dh = khi; dl = klo; }
    else if ((off -= N2_WK) < N2_WK)   { src = wv; dh = vhi; dl = vlo; }
    else { off -= N2_WK;                 src = wo; dh = ohi; dl = olo; }

    float2 v = src[off];
    __half h0 = __float2half(v.x);
    __half h1 = __float2half(v.y);
    __half2 hh; hh.x = h0; hh.y = h1;
    __half2 ll;
    ll.x = __float2half(v.x - __half2float(h0));
    ll.y = __float2half(v.y - __half2float(h1));
    dh[off] = hh;
    dl[off] = ll;
}

// ---------------------------------------------------------------------------
// PTX helpers
// ---------------------------------------------------------------------------
#define CP16(dst, src) \
    asm volatile("cp.async.cg.shared.global [%0], [%1], 16;\n" :: "r"(dst), "l"(src))
#define CP_COMMIT() asm volatile("cp.async.commit_group;\n" ::)
#define CP_WAIT2()  asm volatile("cp.async.wait_group 2;\n" ::)
#define CP_WAIT1()  asm volatile("cp.async.wait_group 1;\n" ::)
#define CP_WAIT0()  asm volatile("cp.async.wait_group 0;\n" ::)

#define LDSM4(R, addr) \
    asm volatile("ldmatrix.sync.aligned.m8n8.x4.shared.b16 {%0,%1,%2,%3}, [%4];\n" \
        : "=r"(R[0]), "=r"(R[1]), "=r"(R[2]), "=r"(R[3]) : "r"(addr))
#define LDSM4T(R, addr) \
    asm volatile("ldmatrix.sync.aligned.m8n8.x4.trans.shared.b16 {%0,%1,%2,%3}, [%4];\n" \
        : "=r"(R[0]), "=r"(R[1]), "=r"(R[2]), "=r"(R[3]) : "r"(addr))

// bf16 mma (attention)
#define MMA16816(acc, a, b0, b1) \
    asm volatile("mma.sync.aligned.m16n8k16.row.col.f32.bf16.bf16.f32 " \
        "{%0,%1,%2,%3}, {%4,%5,%6,%7}, {%8,%9}, {%0,%1,%2,%3};\n" \
        : "+f"(acc[0]), "+f"(acc[1]), "+f"(acc[2]), "+f"(acc[3]) \
        : "r"(a[0]), "r"(a[1]), "r"(a[2]), "r"(a[3]), "r"(b0), "r"(b1))

// fp16 mma (GEMMs)
#define MMAF16(acc, a, b0, b1) \
    asm volatile("mma.sync.aligned.m16n8k16.row.col.f32.f16.f16.f32 " \
        "{%0,%1,%2,%3}, {%4,%5,%6,%7}, {%8,%9}, {%0,%1,%2,%3};\n" \
        : "+f"(acc[0]), "+f"(acc[1]), "+f"(acc[2]), "+f"(acc[3]) \
        : "r"(a[0]), "r"(a[1]), "r"(a[2]), "r"(a[3]), "r"(b0), "r"(b1))

// ---------------------------------------------------------------------------
// GEMM core (fp16 2-pass): C = Ah@Bh^T + Ah@Bl^T   (fp32 accum)
// CTA 128x128, 8 warps, 4-stage cp.async pipeline (Ah|Bh|Bl per stage),
// 1 barrier/K16, 2 CTAs/SM.
// mode 0: fp32 C out. mode 1: bf16 hi/lo out. mode 2: rope+rms -> bf16 hi/lo.
// mode 3: fp16 hi/lo out.
// ---------------------------------------------------------------------------
#define SSTR   24                       // fp16 per smem row (48B, conflict-free)
#define TILE_B (128u * SSTR * 2u)       // 6144 B
#define STG_B  (3u * TILE_B)            // Ah|Bh|Bl = 18432 B
#define G_SMEM (4u * STG_B)             // 73728 B

__device__ __forceinline__ void gemm_core(
    const __half* __restrict__ Ah,
    const __half* __restrict__ Bh, const __half* __restrict__ Bl,
    float* __restrict__ C,
    __nv_bfloat16* __restrict__ Cbh, __nv_bfloat16* __restrict__ Cbl,
    __half* __restrict__ Chh, __half* __restrict__ Chl,
    int N, int K, int bm, int bn, char* smem, int mode,
    const float* __restrict__ cs, const float* __restrict__ sn)
{
    const uint32_t sb = (uint32_t)__cvta_generic_to_shared(smem);
    const int tid = threadIdx.x;
    const int lane = tid & 31;
    const int wid = tid >> 5;
    const int wm = wid & 1;
    const int wn = wid >> 1;

    const int lrow = tid >> 1;
    const int lkc  = tid & 1;
    const __half* gah = Ah + (size_t)(bm * 128 + lrow) * K + lkc * 8;
    const __half* gbh = Bh + (size_t)(bn * 128 + lrow) * K + lkc * 8;
    const __half* gbl = Bl + (size_t)(bn * 128 + lrow) * K + lkc * 8;
    const uint32_t sOff = (uint32_t)(lrow * SSTR + lkc * 8) * 2;

    const uint32_t aLn = (uint32_t)((wm * 64 + (lane & 15)) * SSTR + (lane >> 4) * 8) * 2;
    const uint32_t bLn = (uint32_t)((wn * 32 + ((lane >> 4) << 3) + (lane & 7)) * SSTR
                                    + ((lane >> 3) & 1) * 8) * 2;

    float acc[4][4][4];
    #pragma unroll
    for (int i = 0; i < 4; i++)
        #pragma unroll
        for (int j = 0; j < 4; j++)
            #pragma unroll
            for (int r = 0; r < 4; r++) acc[i][j][r] = 0.f;

    const int T = K / 16;

    auto stage_load = [&](uint32_t st, int kt) {
        uint32_t base = sb + st * STG_B + sOff;
        CP16(base,              gah + kt * 16);
        CP16(base + TILE_B,     gbh + kt * 16);
        CP16(base + 2 * TILE_B, gbl + kt * 16);
        CP_COMMIT();
    };

    stage_load(0, 0);
    stage_load(1, 1);
    stage_load(2, 2);

    for (int t = 0; t < T; t++) {
        CP_WAIT2();
        __syncthreads();

        const uint32_t ab = sb + (uint32_t)(t & 3) * STG_B;
        const uint32_t bb = ab + TILE_B;

        uint32_t ah[4][4], bh[2][4], bl[2][4];
        #pragma unroll
        for (int mt = 0; mt < 4; mt++)
            LDSM4(ah[mt], ab + aLn + mt * (16 * SSTR * 2));
        #pragma unroll
        for (int pr = 0; pr < 2; pr++) {
            LDSM4(bh[pr], bb + bLn + pr * (16 * SSTR * 2));
            LDSM4(bl[pr], bb + TILE_B + bLn + pr * (16 * SSTR * 2));
        }

        if (t + 3 < T) stage_load((uint32_t)((t + 3) & 3), t + 3);
        else           CP_COMMIT();

        // 2 passes, 16 independent chains each
        #pragma unroll
        for (int mt = 0; mt < 4; mt++)
            #pragma unroll
            for (int nt = 0; nt < 4; nt++) {
                const int pr = nt >> 1, q = (nt & 1) * 2;
                MMAF16(acc[mt][nt], ah[mt], bh[pr][q], bh[pr][q + 1]);
            }
        #pragma unroll
        for (int mt = 0; mt < 4; mt++)
            #pragma unroll
            for (int nt = 0; nt < 4; nt++) {
                const int pr = nt >> 1, q = (nt & 1) * 2;
                MMAF16(acc[mt][nt], ah[mt], bl[pr][q], bl[pr][q + 1]);
            }
    }

    if (mode == 0) {
        #pragma unroll
        for (int mt = 0; mt < 4; mt++) {
            const int r0 = bm * 128 + wm * 64 + mt * 16 + (lane >> 2);
            #pragma unroll
            for (int nt = 0; nt < 4; nt++) {
                const int c0 = bn * 128 + wn * 32 + nt * 8 + (lane & 3) * 2;
                *(float2*)&C[(size_t)r0 * N + c0] =
                    make_float2(acc[mt][nt][0], acc[mt][nt][1]);
                *(float2*)&C[(size_t)(r0 + 8) * N + c0] =
                    make_float2(acc[mt][nt][2], acc[mt][nt][3]);
            }
        }
    } else if (mode == 1) {
        #pragma unroll
        for (int mt = 0; mt < 4; mt++) {
            const int r0 = bm * 128 + wm * 64 + mt * 16 + (lane >> 2);
            #pragma unroll
            for (int nt = 0; nt < 4; nt++) {
                const int c0 = bn * 128 + wn * 32 + nt * 8 + (lane & 3) * 2;
                #pragma unroll
                for (int half2i = 0; half2i < 2; half2i++) {
                    float x0 = acc[mt][nt][half2i * 2];
                    float x1 = acc[mt][nt][half2i * 2 + 1];
                    __nv_bfloat162 hh = __floats2bfloat162_rn(x0, x1);
                    __nv_bfloat162 ll = __floats2bfloat162_rn(
                        x0 - __bfloat162float(hh.x), x1 - __bfloat162float(hh.y));
                    size_t off = (size_t)(r0 + half2i * 8) * N + c0;
                    *(uint32_t*)&Cbh[off] = *(uint32_t*)&hh;
                    *(uint32_t*)&Cbl[off] = *(uint32_t*)&ll;
                }
            }
        }
    } else {
        // mode 2: rope + rmsnorm fused epilogue -> bf16 hi/lo
        CP_WAIT0();
        __syncthreads();
        float* st = (float*)smem;               // 128 x 132 fp32 (67.6 KB)
        #pragma unroll
        for (int mt = 0; mt < 4; mt++) {
            const int r0 = wm * 64 + mt * 16 + (lane >> 2);
            #pragma unroll
            for (int nt = 0; nt < 4; nt++) {
                const int c0 = wn * 32 + nt * 8 + (lane & 3) * 2;
                *(float2*)&st[r0 * 132 + c0] =
                    make_float2(acc[mt][nt][0], acc[mt][nt][1]);
                *(float2*)&st[(r0 + 8) * 132 + c0] =
                    make_float2(acc[mt][nt][2], acc[mt][nt][3]);
            }
        }
        __syncthreads();

        const int cb = bn * 128;
        for (int rr = 0; rr < 16; rr++) {
            int r = wid * 16 + rr;
            int grow_ = bm * 128 + r;
            int s = grow_ & (S_ - 1);
            float x1a = st[r * 132 + lane],      x1b = st[r * 132 + lane + 32];
            float x2a = st[r * 132 + lane + 64], x2b = st[r * 132 + lane + 96];
            float ca = cs[s * 64 + lane], cbv = cs[s * 64 + lane + 32];
            float sa = sn[s * 64 + lane], sbv = sn[s * 64 + lane + 32];

            float o1a =  x1a * ca  + x2a * sa;
            float o1b =  x1b * cbv + x2b * sbv;
            float o2a = -x1a * sa  + x2a * ca;
            float o2b = -x1b * sbv + x2b * cbv;

            float ss = o1a * o1a + o1b * o1b + o2a * o2a + o2b * o2b;
            #pragma unroll
            for (int o = 16; o; o >>= 1) ss += __shfl_xor_sync(0xffffffffu, ss, o);
            float scale = rsqrtf(ss * (1.f / 128.f) + 1.1920928955078125e-07f);

            float v4[4] = {o1a * scale, o1b * scale, o2a * scale, o2b * scale};
            size_t gb = (size_t)grow_ * N + cb + lane;
            #pragma unroll
            for (int u = 0; u < 4; u++) {
                __nv_bfloat16 hh = __float2bfloat16(v4[u]);
                Cbh[gb + u * 32] = hh;
                Cbl[gb + u * 32] = __float2bfloat16(v4[u] - __bfloat162float(hh));
            }
        }
    }
}

// Fused Q/K/V projection + rope/rms epilogue for Q,K; bf16 split for V.
__global__ __launch_bounds__(256, 2) void gemm_qkv(
    const __half* __restrict__ xh,
    const __half* __restrict__ wqh, const __half* __restrict__ wql,
    const __half* __restrict__ wkh, const __half* __restrict__ wkl,
    const __half* __restrict__ wvh, const __half* __restrict__ wvl,
    __nv_bfloat16* __restrict__ qhi, __nv_bfloat16* __restrict__ qlo,
    __nv_bfloat16* __restrict__ khi, __nv_bfloat16* __restrict__ klo,
    __nv_bfloat16* __restrict__ vhi, __nv_bfloat16* __restrict__ vlo,
    const float* __restrict__ cosp, const float* __restrict__ sinp)
{
    extern __shared__ char smem[];
    const int bx = blockIdx.x;
    if (bx < 16) {
        gemm_core(xh, wqh, wql, nullptr, qhi, qlo, nullptr, nullptr,
                  H_ * D_, E_, blockIdx.y, bx, smem, 2, cosp, sinp);
    } else if (bx < 20) {
        gemm_core(xh, wkh, wkl, nullptr, khi, klo, nullptr, nullptr,
                  KV_ * D_, E_, blockIdx.y, bx - 16, smem, 2, cosp, sinp);
    } else {
        gemm_core(xh, wvh, wvl, nullptr, vhi, vlo, nullptr, nullptr,
                  KV_ * D_, E_, blockIdx.y, bx - 20, smem, 1, nullptr, nullptr);
    }
}

__global__ __launch_bounds__(256, 2) void gemm_one(
    const __half* __restrict__ Ah,
    const __half* __restrict__ Bh, const __half* __restrict__ Bl,
    float* __restrict__ C, int N, int K)
{
    extern __shared__ char smem[];
    gemm_core(Ah, Bh, Bl, C, nullptr, nullptr, nullptr, nullptr, N, K,
              blockIdx.y, blockIdx.x, smem, 0, nullptr, nullptr);
}

// ---------------------------------------------------------------------------
// Tensor-core sliding-window flash attention (bf16 3-pass, as R3).
// Epilogue writes ctx as fp16 hi/lo for the fp16 out-projection.
// ---------------------------------------------------------------------------
#define RB 17408   // 64 rows * 272 B (stride 136 bf16)

__global__ __launch_bounds__(256) void attn_mma(
    const __nv_bfloat16* __restrict__ qh, const __nv_bfloat16* __restrict__ ql,
    const __nv_bfloat16* __restrict__ kh, const __nv_bfloat16* __restrict__ kl,
    const __nv_bfloat16* __restrict__ vh, const __nv_bfloat16* __restrict__ vl,
    __half* __restrict__ chi, __half* __restrict__ clo)
{
    extern __shared__ char smem[];
    const uint32_t sbase = (uint32_t)__cvta_generic_to_shared(smem);

    const int tid = threadIdx.x, lane = tid & 31, w = tid >> 5;
    const int q0 = blockIdx.x * 128;
    const int h  = blockIdx.y, b = blockIdx.z;
    const int kvh = h >> 2;
    const float scl = 0.08838834764831845f;

    {
        int r = tid >> 1;
        size_t gbase = ((size_t)(b * S_ + q0 + r)) * (H_ * D_) + h * D_;
        const uint4* gh = (const uint4*)(qh + gbase);
        const uint4* gl = (const uint4*)(ql + gbase);
        #pragma unroll
        for (int u = 0; u < 8; u++) {
            int c = (tid & 1) * 8 + u;
            *(uint4*)(smem + (size_t)r * 272 + c * 16)            = gh[c];
            *(uint4*)(smem + 4 * RB + (size_t)r * 272 + c * 16)   = gl[c];
        }
    }
    __syncthreads();

    uint32_t ah[8][4], al[8][4];
    {
        uint32_t qro = (uint32_t)((w * 16 + (lane & 15)) * 272);
        #pragma unroll
        for (int d = 0; d < 8; d++) {
            uint32_t co = (uint32_t)((d * 16 + (lane >> 4) * 8) * 2);
            LDSM4(ah[d], sbase + qro + co);
            LDSM4(al[d], sbase + 4 * RB + qro + co);
        }
    }
    __syncthreads();

    float pacc[16][4];
    #pragma unroll
    for (int g = 0; g < 16; g++)
        #pragma unroll
        for (int r = 0; r < 4; r++) pacc[g][r] = 0.f;

    float m_run0 = -1e30f, m_run1 = -1e30f, l0 = 0.f, l1 = 0.f;

    const int ibase = q0 + w * 16;
    const int i0 = ibase + (lane >> 2);
    const int i1 = i0 + 8;

    int t0 = q0 - 1024; if (t0 < 0) t0 = 0;
    const int n = (q0 + 128 - t0) >> 6;

    const int crow = tid >> 2;
    const size_t grow = ((size_t)b * S_) * (KV_ * D_) + (size_t)kvh * D_;

    {
        size_t gb = grow + (size_t)(t0 + crow) * (KV_ * D_);
        #pragma unroll
        for (int u = 0; u < 4; u++) {
            int c = (tid & 3) * 4 + u;
            uint32_t so = (uint32_t)(crow * 272 + c * 16);
            CP16(sbase + so,          kh + gb + c * 8);
            CP16(sbase + 2 * RB + so, kl + gb + c * 8);
            CP16(sbase + 4 * RB + so, vh + gb + c * 8);
            CP16(sbase + 6 * RB + so, vl + gb + c * 8);
        }
        CP_COMMIT();
    }

    for (int it = 0; it < n; it++) {
        const int t = t0 + it * 64;
        if (it + 1 < n) {
            int st = (it + 1) & 1;
            size_t gb = grow + (size_t)(t + 64 + crow) * (KV_ * D_);
            #pragma unroll
            for (int u = 0; u < 4; u++) {
                int c = (tid & 3) * 4 + u;
                uint32_t so = (uint32_t)(st * RB + crow * 272 + c * 16);
                CP16(sbase + so,          kh + gb + c * 8);
                CP16(sbase + 2 * RB + so, kl + gb + c * 8);
                CP16(sbase + 4 * RB + so, vh + gb + c * 8);
                CP16(sbase + 6 * RB + so, vl + gb + c * 8);
            }
            CP_COMMIT();
            CP_WAIT1();
        } else {
            CP_WAIT0();
        }
        __syncthreads();

        const uint32_t khb = sbase + (it & 1) * RB;
        const uint32_t klb = khb + 2 * RB;
        const uint32_t vhb = khb + 4 * RB;
        const uint32_t vlb = khb + 6 * RB;

        float sacc[8][4];
        #pragma unroll
        for (int g = 0; g < 8; g++)
            #pragma unroll
            for (int r = 0; r < 4; r++) sacc[g][r] = 0.f;

        #pragma unroll
        for (int d = 0; d < 8; d++) {
            uint32_t co = (uint32_t)((d * 16 + ((lane >> 3) & 1) * 8) * 2);
            #pragma unroll
            for (int g = 0; g < 4; g++) {
                uint32_t ro = (uint32_t)((g * 16 + ((lane >> 4) << 3) + (lane & 7)) * 272);
                uint32_t k4h[4], k4l[4];
                LDSM4(k4h, khb + ro + co);
                LDSM4(k4l, klb + ro + co);
                MMA16816(sacc[2 * g],     ah[d], k4h[0], k4h[1]);
                MMA16816(sacc[2 * g],     ah[d], k4l[0], k4l[1]);
                MMA16816(sacc[2 * g],     al[d], k4h[0], k4h[1]);
                MMA16816(sacc[2 * g + 1], ah[d], k4h[2], k4h[3]);
                MMA16816(sacc[2 * g + 1], ah[d], k4l[2], k4l[3]);
                MMA16816(sacc[2 * g + 1], al[d], k4h[2], k4h[3]);
            }
        }

        const bool need_mask = (t + 63 >= ibase) || (t + 1009 <= ibase);
        float m0 = -INFINITY, m1 = -INFINITY;
        #pragma unroll
        for (int g = 0; g < 8; g++) {
            int jb = t + g * 8 + 2 * (lane & 3);
            float s0 = sacc[g][0] * scl, s1 = sacc[g][1] * scl;
            float s2 = sacc[g][2] * scl, s3 = sacc[g][3] * scl;
            if (need_mask) {
                s0 = ((jb     <= i0) && (i0 - jb < 1024))     ? s0 : -INFINITY;
                s1 = ((jb + 1 <= i0) && (i0 - jb - 1 < 1024)) ? s1 : -INFINITY;
                s2 = ((jb     <= i1) && (i1 - jb < 1024))     ? s2 : -INFINITY;
                s3 = ((jb + 1 <= i1) && (i1 - jb - 1 < 1024)) ? s3 : -INFINITY;
            }
            sacc[g][0] = s0; sacc[g][1] = s1; sacc[g][2] = s2; sacc[g][3] = s3;
            m0 = fmaxf(m0, fmaxf(s0, s1));
            m1 = fmaxf(m1, fmaxf(s2, s3));
        }
        m0 = fmaxf(m0, __shfl_xor_sync(0xffffffffu, m0, 1));
        m0 = fmaxf(m0, __shfl_xor_sync(0xffffffffu, m0, 2));
        m1 = fmaxf(m1, __shfl_xor_sync(0xffffffffu, m1, 1));
        m1 = fmaxf(m1, __shfl_xor_sync(0xffffffffu, m1, 2));

        float mn0 = fmaxf(m_run0, m0), mn1 = fmaxf(m_run1, m1);
        float a0 = __expf(m_run0 - mn0), a1 = __expf(m_run1 - mn1);
        m_run0 = mn0; m_run1 = mn1;

        float rs0 = 0.f, rs1 = 0.f;
        #pragma unroll
        for (int g = 0; g < 8; g++) {
            float p0 = __expf(sacc[g][0] - mn0);
            float p1 = __expf(sacc[g][1] - mn0);
            float p2 = __expf(sacc[g][2] - mn1);
            float p3 = __expf(sacc[g][3] - mn1);
            sacc[g][0] = p0; sacc[g][1] = p1; sacc[g][2] = p2; sacc[g][3] = p3;
            rs0 += p0 + p1; rs1 += p2 + p3;
        }
        rs0 += __shfl_xor_sync(0xffffffffu, rs0, 1);
        rs0 += __shfl_xor_sync(0xffffffffu, rs0, 2);
        rs1 += __shfl_xor_sync(0xffffffffu, rs1, 1);
        rs1 += __shfl_xor_sync(0xffffffffu, rs1, 2);
        l0 = l0 * a0 + rs0;
        l1 = l1 * a1 + rs1;

        #pragma unroll
        for (int g = 0; g < 16; g++) {
            pacc[g][0] *= a0; pacc[g][1] *= a0;
            pacc[g][2] *= a1; pacc[g][3] *= a1;
        }

        uint32_t ph[4][4], pl[4][4];
        #pragma unroll
        for (int kt = 0; kt < 4; kt++) {
            #pragma unroll
            for (int qq = 0; qq < 2; qq++) {
                #pragma unroll
                for (int r2 = 0; r2 < 2; r2++) {
                    float x0 = sacc[2 * kt + qq][r2 * 2];
                    float x1 = sacc[2 * kt + qq][r2 * 2 + 1];
                    __nv_bfloat162 hh = __floats2bfloat162_rn(x0, x1);
                    __nv_bfloat162 ll = __floats2bfloat162_rn(
                        x0 - __bfloat162float(hh.x), x1 - __bfloat162float(hh.y));
                    ph[kt][qq * 2 + r2] = *(uint32_t*)&hh;
                    pl[kt][qq * 2 + r2] = *(uint32_t*)&ll;
                }
            }
        }

        #pragma unroll
        for (int kt = 0; kt < 4; kt++) {
            uint32_t ro = (uint32_t)((kt * 16 + (lane & 15)) * 272);
            uint32_t co = (uint32_t)(((lane >> 4) * 8) * 2);
            #pragma unroll
            for (int g = 0; g < 8; g++) {
                uint32_t v4h[4], v4l[4];
                LDSM4T(v4h, vhb + ro + co + g * 32);
                LDSM4T(v4l, vlb + ro + co + g * 32);
                MMA16816(pacc[2 * g],     ph[kt], v4h[0], v4h[1]);
                MMA16816(pacc[2 * g],     pl[kt], v4h[0], v4h[1]);
                MMA16816(pacc[2 * g],     ph[kt], v4l[0], v4l[1]);
                MMA16816(pacc[2 * g + 1], ph[kt], v4h[2], v4h[3]);
                MMA16816(pacc[2 * g + 1], pl[kt], v4h[2], v4h[3]);
                MMA16816(pacc[2 * g + 1], ph[kt], v4l[2], v4l[3]);
            }
        }
        __syncthreads();
    }

    float inv0 = 1.f / l0, inv1 = 1.f / l1;
    size_t base0 = ((size_t)(b * S_ + i0)) * (H_ * D_) + h * D_;
    size_t base1 = base0 + (size_t)8 * (H_ * D_);
    #pragma unroll
    for (int g = 0; g < 16; g++) {
        int col = g * 8 + 2 * (lane & 3);
        float o0 = pacc[g][0] * inv0, o1 = pacc[g][1] * inv0;
        float o2 = pacc[g][2] * inv1, o3 = pacc[g][3] * inv1;
        __half2 h0 = __floats2half2_rn(o0, o1);
        __half2 l0v = __floats2half2_rn(
            o0 - __half2float(h0.x), o1 - __half2float(h0.y));
        __half2 h1 = __floats2half2_rn(o2, o3);
        __half2 l1v = __floats2half2_rn(
            o2 - __half2float(h1.x), o3 - __half2float(h1.y));
        *(uint32_t*)&chi[base0 + col] = *(uint32_t*)&h0;
        *(uint32_t*)&clo[base0 + col] = *(uint32_t*)&l0v;
        *(uint32_t*)&chi[base1 + col] = *(uint32_t*)&h1;
        *(uint32_t*)&clo[base1 + col] = *(uint32_t*)&l1v;
    }
}

// ---------------------------------------------------------------------------
extern "C" void kernel_launch(void* const* d_in, const int* in_sizes, int n_in,
                              void* d_out, int out_size)
{
    const float* x    = (const float*)d_in[0];
    const float* cosp = (const float*)d_in[1];
    const float* sinp = (const float*)d_in[2];
    const float* Wq   = (const float*)d_in[3];
    const float* Wk   = (const float*)d_in[4];
    const float* Wv   = (const float*)d_in[5];
    const float* Wo   = (const float*)d_in[6];
    float* out = (float*)d_out;

    __half *xhi, *xlo, *wqhi, *wqlo, *wkhi, *wklo, *wvhi, *wvlo, *wohi, *wolo;
    __half *chi, *clo;
    __nv_bfloat16 *qhi, *qlo, *khi, *klo, *vhi, *vlo;
    cudaGetSymbolAddress((void**)&xhi, g_xhi);
    cudaGetSymbolAddress((void**)&xlo, g_xlo);
    cudaGetSymbolAddress((void**)&wqhi, g_wqhi);
    cudaGetSymbolAddress((void**)&wqlo, g_wqlo);
    cudaGetSymbolAddress((void**)&wkhi, g_wkhi);
    cudaGetSymbolAddress((void**)&wklo, g_wklo);
    cudaGetSymbolAddress((void**)&wvhi, g_wvhi);
    cudaGetSymbolAddress((void**)&wvlo, g_wvlo);
    cudaGetSymbolAddress((void**)&wohi, g_wohi);
    cudaGetSymbolAddress((void**)&wolo, g_wolo);
    cudaGetSymbolAddress((void**)&chi, g_chi);
    cudaGetSymbolAddress((void**)&clo, g_clo);
    cudaGetSymbolAddress((void**)&qhi, g_qhi);
    cudaGetSymbolAddress((void**)&qlo, g_qlo);
    cudaGetSymbolAddress((void**)&khi, g_khi);
    cudaGetSymbolAddress((void**)&klo, g_klo);
    cudaGetSymbolAddress((void**)&vhi, g_vhi);
    cudaGetSymbolAddress((void**)&vlo, g_vlo);

    static bool attr_done = false;
    if (!attr_done) {
        cudaFuncSetAttribute(attn_mma,
            cudaFuncAttributeMaxDynamicSharedMemorySize, 8 * RB);
        cudaFuncSetAttribute(gemm_qkv,
            cudaFuncAttributeMaxDynamicSharedMemorySize, G_SMEM);
        cudaFuncSetAttribute(gemm_one,
            cudaFuncAttributeMaxDynamicSharedMemorySize, G_SMEM);
        attr_done = true;
    }

    const int M = B_ * S_;

    // one fused split launch (fp16 hi/lo)
    {
        size_t blocks = (N2_ALL + 255) / 256;
        split_all<<<(unsigned)blocks, 256>>>(
            (const float2*)x, (const float2*)Wq, (const float2*)Wk,
            (const float2*)Wv, (const float2*)Wo,
            (__half2*)xhi,  (__half2*)xlo,
            (__half2*)wqhi, (__half2*)wqlo,
            (__half2*)wkhi, (__half2*)wklo,
            (__half2*)wvhi, (__half2*)wvlo,
            (__half2*)wohi, (__half2*)wolo);
    }

    // fused Q/K/V projections + rope/rms epilogue (Q,K) + bf16 split (V)
    gemm_qkv<<<dim3(24, M / 128), 256, G_SMEM>>>(
        xhi, wqhi, wqlo, wkhi, wklo, wvhi, wvlo,
        qhi, qlo, khi, klo, vhi, vlo, cosp, sinp);

    // attention (bf16 3-pass; ctx out as fp16 hi/lo)
    attn_mma<<<dim3(S_ / 128, H_, B_), 256, 8 * RB>>>(
        qhi, qlo, khi, klo, vhi, vlo, chi, clo);

    // output projection (fp16 2-pass)
    gemm_one<<<dim3(E_ / 128, M / 128), 256, G_SMEM>>>(
        chi, wohi, wolo, out, E_, E_);
}

// round 10
// speedup vs baseline: 1.7682x; 1.1054x over previous
#include <cuda_runtime.h>
#include <cuda_bf16.h>
#include <cuda_fp16.h>
#include <math.h>
#include <stdint.h>

#define B_  2
#define S_  2048
#define E_  2048
#define H_  16
#define KV_ 4
#define D_  128
#define WIN_ 1024

// fp16 hi/lo scratch (GEMM operands)
__device__ __half g_xhi[(size_t)B_ * S_ * E_];
__device__ __half g_xlo[(size_t)B_ * S_ * E_];
__device__ __half g_wqhi[(size_t)H_ * D_ * E_];
__device__ __half g_wqlo[(size_t)H_ * D_ * E_];
__device__ __half g_wkhi[(size_t)KV_ * D_ * E_];
__device__ __half g_wklo[(size_t)KV_ * D_ * E_];
__device__ __half g_wvhi[(size_t)KV_ * D_ * E_];
__device__ __half g_wvlo[(size_t)KV_ * D_ * E_];
__device__ __half g_wohi[(size_t)E_ * H_ * D_];
__device__ __half g_wolo[(size_t)E_ * H_ * D_];
__device__ __half g_chi[(size_t)B_ * S_ * H_ * D_];
__device__ __half g_clo[(size_t)B_ * S_ * H_ * D_];

// fp16 attention operands (2-pass compensated)
__device__ __half g_qh[(size_t)B_ * S_ * H_ * D_];
__device__ __half g_kh[(size_t)B_ * S_ * KV_ * D_];
__device__ __half g_kl[(size_t)B_ * S_ * KV_ * D_];
__device__ __half g_vh[(size_t)B_ * S_ * KV_ * D_];

// ---------------------------------------------------------------------------
// Fused fp16 hi/lo splitter for x, Wq, Wk, Wv, Wo (one launch). float2 units.
// ---------------------------------------------------------------------------
#define N2_X  ((size_t)B_ * S_ * E_ / 2)
#define N2_WQ ((size_t)H_ * D_ * E_ / 2)
#define N2_WK ((size_t)KV_ * D_ * E_ / 2)
#define N2_ALL (N2_X + 2 * N2_WQ + 2 * N2_WK)

__global__ __launch_bounds__(256) void split_all(
    const float2* __restrict__ x,  const float2* __restrict__ wq,
    const float2* __restrict__ wk, const float2* __restrict__ wv,
    const float2* __restrict__ wo,
    __half2* __restrict__ xhi,  __half2* __restrict__ xlo,
    __half2* __restrict__ qhi,  __half2* __restrict__ qlo,
    __half2* __restrict__ khi,  __half2* __restrict__ klo,
    __half2* __restrict__ vhi,  __half2* __restrict__ vlo,
    __half2* __restrict__ ohi,  __half2* __restrict__ olo)
{
    size_t i = (size_t)blockIdx.x * blockDim.x + threadIdx.x;
    if (i >= N2_ALL) return;

    const float2* src;
    __half2 *dh, *dl;
    size_t off = i;
    if (off < N2_X)                    { src = x;  dh = xhi; dl = xlo; }
    else if ((off -= N2_X) < N2_WQ)    { src = wq; dh = qhi; dl = qlo; }
    else if ((off -= N2_WQ) < N2_WK)   { src = wk; dh = khi; dl = klo; }
    else if ((off -= N2_WK) < N2_WK)   { src = wv; dh = vhi; dl = vlo; }
    else { off -= N2_WK;                 src = wo; dh = ohi; dl = olo; }

    float2 v = src[off];
    __half h0 = __float2half(v.x);
    __half h1 = __float2half(v.y);
    __half2 hh; hh.x = h0; hh.y = h1;
    __half2 ll;
    ll.x = __float2half(v.x - __half2float(h0));
    ll.y = __float2half(v.y - __half2float(h1));
    dh[off] = hh;
    dl[off] = ll;
}

// ---------------------------------------------------------------------------
// PTX helpers
// ---------------------------------------------------------------------------
#define CP16(dst, src) \
    asm volatile("cp.async.cg.shared.global [%0], [%1], 16;\n" :: "r"(dst), "l"(src))
#define CP_COMMIT() asm volatile("cp.async.commit_group;\n" ::)
#define CP_WAIT2()  asm volatile("cp.async.wait_group 2;\n" ::)
#define CP_WAIT1()  asm volatile("cp.async.wait_group 1;\n" ::)
#define CP_WAIT0()  asm volatile("cp.async.wait_group 0;\n" ::)

#define LDSM4(R, addr) \
    asm volatile("ldmatrix.sync.aligned.m8n8.x4.shared.b16 {%0,%1,%2,%3}, [%4];\n" \
        : "=r"(R[0]), "=r"(R[1]), "=r"(R[2]), "=r"(R[3]) : "r"(addr))
#define LDSM4T(R, addr) \
    asm volatile("ldmatrix.sync.aligned.m8n8.x4.trans.shared.b16 {%0,%1,%2,%3}, [%4];\n" \
        : "=r"(R[0]), "=r"(R[1]), "=r"(R[2]), "=r"(R[3]) : "r"(addr))

// fp16 mma
#define MMAF16(acc, a, b0, b1) \
    asm volatile("mma.sync.aligned.m16n8k16.row.col.f32.f16.f16.f32 " \
        "{%0,%1,%2,%3}, {%4,%5,%6,%7}, {%8,%9}, {%0,%1,%2,%3};\n" \
        : "+f"(acc[0]), "+f"(acc[1]), "+f"(acc[2]), "+f"(acc[3]) \
        : "r"(a[0]), "r"(a[1]), "r"(a[2]), "r"(a[3]), "r"(b0), "r"(b1))

// ---------------------------------------------------------------------------
// GEMM core (fp16 2-pass): C = Ah@Bh^T + Ah@Bl^T   (fp32 accum)
// CTA 128x128, 8 warps, 6-stage cp.async pipeline, 2 K16-substeps per
// barrier, 2 CTAs/SM.
// mode 0: fp32 out. mode 1: fp16 hi out. mode 2: rope+rms -> fp16 hi (+lo).
// ---------------------------------------------------------------------------
#define SSTR   24                       // fp16 per smem row (48B, conflict-free)
#define TILE_B (128u * SSTR * 2u)       // 6144 B
#define STG_B  (3u * TILE_B)            // Ah|Bh|Bl = 18432 B
#define G_SMEM (6u * STG_B)             // 110592 B

__device__ __forceinline__ void gemm_core(
    const __half* __restrict__ Ah,
    const __half* __restrict__ Bh, const __half* __restrict__ Bl,
    float* __restrict__ C,
    __half* __restrict__ Chh, __half* __restrict__ Chl,
    int N, int K, int bm, int bn, char* smem, int mode,
    const float* __restrict__ cs, const float* __restrict__ sn)
{
    const uint32_t sb = (uint32_t)__cvta_generic_to_shared(smem);
    const int tid = threadIdx.x;
    const int lane = tid & 31;
    const int wid = tid >> 5;
    const int wm = wid & 1;
    const int wn = wid >> 1;

    const int lrow = tid >> 1;
    const int lkc  = tid & 1;
    const __half* gah = Ah + (size_t)(bm * 128 + lrow) * K + lkc * 8;
    const __half* gbh = Bh + (size_t)(bn * 128 + lrow) * K + lkc * 8;
    const __half* gbl = Bl + (size_t)(bn * 128 + lrow) * K + lkc * 8;
    const uint32_t sOff = (uint32_t)(lrow * SSTR + lkc * 8) * 2;

    const uint32_t aLn = (uint32_t)((wm * 64 + (lane & 15)) * SSTR + (lane >> 4) * 8) * 2;
    const uint32_t bLn = (uint32_t)((wn * 32 + ((lane >> 4) << 3) + (lane & 7)) * SSTR
                                    + ((lane >> 3) & 1) * 8) * 2;

    float acc[4][4][4];
    #pragma unroll
    for (int i = 0; i < 4; i++)
        #pragma unroll
        for (int j = 0; j < 4; j++)
            #pragma unroll
            for (int r = 0; r < 4; r++) acc[i][j][r] = 0.f;

    const int T = K / 16;           // even for all our K

    auto stage_load = [&](uint32_t st, int kt) {
        uint32_t base = sb + st * STG_B + sOff;
        CP16(base,              gah + kt * 16);
        CP16(base + TILE_B,     gbh + kt * 16);
        CP16(base + 2 * TILE_B, gbl + kt * 16);
        CP_COMMIT();
    };

    stage_load(0, 0);
    stage_load(1, 1);
    stage_load(2, 2);
    stage_load(3, 3);

    const int TP = T / 2;
    for (int j = 0; j < TP; j++) {
        CP_WAIT2();                 // 4 pending -> oldest 2 stages ready
        __syncthreads();
        const uint32_t sA = (uint32_t)((2 * j) % 6);

        // ---- substep A (tile 2j, stage sA) ----
        {
            const uint32_t ab = sb + sA * STG_B;
            const uint32_t bb = ab + TILE_B;
            uint32_t ah[4][4], bh[2][4], bl[2][4];
            #pragma unroll
            for (int mt = 0; mt < 4; mt++)
                LDSM4(ah[mt], ab + aLn + mt * (16 * SSTR * 2));
            #pragma unroll
            for (int pr = 0; pr < 2; pr++) {
                LDSM4(bh[pr], bb + bLn + pr * (16 * SSTR * 2));
                LDSM4(bl[pr], bb + TILE_B + bLn + pr * (16 * SSTR * 2));
            }
            if (2 * j + 4 < T) stage_load((uint32_t)((2 * j + 4) % 6), 2 * j + 4);
            else               CP_COMMIT();

            #pragma unroll
            for (int mt = 0; mt < 4; mt++)
                #pragma unroll
                for (int nt = 0; nt < 4; nt++) {
                    const int pr = nt >> 1, q = (nt & 1) * 2;
                    MMAF16(acc[mt][nt], ah[mt], bh[pr][q], bh[pr][q + 1]);
                }
            #pragma unroll
            for (int mt = 0; mt < 4; mt++)
                #pragma unroll
                for (int nt = 0; nt < 4; nt++) {
                    const int pr = nt >> 1, q = (nt & 1) * 2;
                    MMAF16(acc[mt][nt], ah[mt], bl[pr][q], bl[pr][q + 1]);
                }
        }

        // ---- substep B (tile 2j+1, stage sA+1) ----
        {
            const uint32_t ab = sb + (sA + 1) * STG_B;
            const uint32_t bb = ab + TILE_B;
            uint32_t ah[4][4], bh[2][4], bl[2][4];
            #pragma unroll
            for (int mt = 0; mt < 4; mt++)
                LDSM4(ah[mt], ab + aLn + mt * (16 * SSTR * 2));
            #pragma unroll
            for (int pr = 0; pr < 2; pr++) {
                LDSM4(bh[pr], bb + bLn + pr * (16 * SSTR * 2));
                LDSM4(bl[pr], bb + TILE_B + bLn + pr * (16 * SSTR * 2));
            }
            if (2 * j + 5 < T) stage_load((uint32_t)((2 * j + 5) % 6), 2 * j + 5);
            else               CP_COMMIT();

            #pragma unroll
            for (int mt = 0; mt < 4; mt++)
                #pragma unroll
                for (int nt = 0; nt < 4; nt++) {
                    const int pr = nt >> 1, q = (nt & 1) * 2;
                    MMAF16(acc[mt][nt], ah[mt], bh[pr][q], bh[pr][q + 1]);
                }
            #pragma unroll
            for (int mt = 0; mt < 4; mt++)
                #pragma unroll
                for (int nt = 0; nt < 4; nt++) {
                    const int pr = nt >> 1, q = (nt & 1) * 2;
                    MMAF16(acc[mt][nt], ah[mt], bl[pr][q], bl[pr][q + 1]);
                }
        }
    }

    if (mode == 0) {
        #pragma unroll
        for (int mt = 0; mt < 4; mt++) {
            const int r0 = bm * 128 + wm * 64 + mt * 16 + (lane >> 2);
            #pragma unroll
            for (int nt = 0; nt < 4; nt++) {
                const int c0 = bn * 128 + wn * 32 + nt * 8 + (lane & 3) * 2;
                *(float2*)&C[(size_t)r0 * N + c0] =
                    make_float2(acc[mt][nt][0], acc[mt][nt][1]);
                *(float2*)&C[(size_t)(r0 + 8) * N + c0] =
                    make_float2(acc[mt][nt][2], acc[mt][nt][3]);
            }
        }
    } else if (mode == 1) {
        // fp16 hi only
        #pragma unroll
        for (int mt = 0; mt < 4; mt++) {
            const int r0 = bm * 128 + wm * 64 + mt * 16 + (lane >> 2);
            #pragma unroll
            for (int nt = 0; nt < 4; nt++) {
                const int c0 = bn * 128 + wn * 32 + nt * 8 + (lane & 3) * 2;
                #pragma unroll
                for (int hf = 0; hf < 2; hf++) {
                    __half2 hh = __floats2half2_rn(acc[mt][nt][hf * 2],
                                                   acc[mt][nt][hf * 2 + 1]);
                    *(uint32_t*)&Chh[(size_t)(r0 + hf * 8) * N + c0] =
                        *(uint32_t*)&hh;
                }
            }
        }
    } else {
        // mode 2: rope + rmsnorm fused epilogue -> fp16 hi (+ lo if Chl)
        CP_WAIT0();
        __syncthreads();
        float* st = (float*)smem;               // 128 x 132 fp32
        #pragma unroll
        for (int mt = 0; mt < 4; mt++) {
            const int r0 = wm * 64 + mt * 16 + (lane >> 2);
            #pragma unroll
            for (int nt = 0; nt < 4; nt++) {
                const int c0 = wn * 32 + nt * 8 + (lane & 3) * 2;
                *(float2*)&st[r0 * 132 + c0] =
                    make_float2(acc[mt][nt][0], acc[mt][nt][1]);
                *(float2*)&st[(r0 + 8) * 132 + c0] =
                    make_float2(acc[mt][nt][2], acc[mt][nt][3]);
            }
        }
        __syncthreads();

        const int cb = bn * 128;
        for (int rr = 0; rr < 16; rr++) {
            int r = wid * 16 + rr;
            int grow_ = bm * 128 + r;
            int s = grow_ & (S_ - 1);
            float x1a = st[r * 132 + lane],      x1b = st[r * 132 + lane + 32];
            float x2a = st[r * 132 + lane + 64], x2b = st[r * 132 + lane + 96];
            float ca = cs[s * 64 + lane], cbv = cs[s * 64 + lane + 32];
            float sa = sn[s * 64 + lane], sbv = sn[s * 64 + lane + 32];

            float o1a =  x1a * ca  + x2a * sa;
            float o1b =  x1b * cbv + x2b * sbv;
            float o2a = -x1a * sa  + x2a * ca;
            float o2b = -x1b * sbv + x2b * cbv;

            float ss = o1a * o1a + o1b * o1b + o2a * o2a + o2b * o2b;
            #pragma unroll
            for (int o = 16; o; o >>= 1) ss += __shfl_xor_sync(0xffffffffu, ss, o);
            float scale = rsqrtf(ss * (1.f / 128.f) + 1.1920928955078125e-07f);

            float v4[4] = {o1a * scale, o1b * scale, o2a * scale, o2b * scale};
            size_t gb = (size_t)grow_ * N + cb + lane;
            #pragma unroll
            for (int u = 0; u < 4; u++) {
                __half hh = __float2half(v4[u]);
                Chh[gb + u * 32] = hh;
                if (Chl) Chl[gb + u * 32] =
                    __float2half(v4[u] - __half2float(hh));
            }
        }
    }
}

// Fused Q/K/V projection + rope/rms epilogue (Q: hi, K: hi+lo); V: hi.
__global__ __launch_bounds__(256, 2) void gemm_qkv(
    const __half* __restrict__ xh,
    const __half* __restrict__ wqh, const __half* __restrict__ wql,
    const __half* __restrict__ wkh, const __half* __restrict__ wkl,
    const __half* __restrict__ wvh, const __half* __restrict__ wvl,
    __half* __restrict__ qh, __half* __restrict__ kh, __half* __restrict__ kl,
    __half* __restrict__ vh,
    const float* __restrict__ cosp, const float* __restrict__ sinp)
{
    extern __shared__ char smem[];
    const int bx = blockIdx.x;
    if (bx < 16) {
        gemm_core(xh, wqh, wql, nullptr, qh, nullptr,
                  H_ * D_, E_, blockIdx.y, bx, smem, 2, cosp, sinp);
    } else if (bx < 20) {
        gemm_core(xh, wkh, wkl, nullptr, kh, kl,
                  KV_ * D_, E_, blockIdx.y, bx - 16, smem, 2, cosp, sinp);
    } else {
        gemm_core(xh, wvh, wvl, nullptr, vh, nullptr,
                  KV_ * D_, E_, blockIdx.y, bx - 20, smem, 1, nullptr, nullptr);
    }
}

__global__ __launch_bounds__(256, 2) void gemm_one(
    const __half* __restrict__ Ah,
    const __half* __restrict__ Bh, const __half* __restrict__ Bl,
    float* __restrict__ C, int N, int K)
{
    extern __shared__ char smem[];
    gemm_core(Ah, Bh, Bl, C, nullptr, nullptr, N, K,
              blockIdx.y, blockIdx.x, smem, 0, nullptr, nullptr);
}

// ---------------------------------------------------------------------------
// fp16 2-pass sliding-window flash attention.
//   S = Qh (Kh + Kl)^T ;  O = (Ph + Pl) Vh
// Stages: Kh | Kl | Vh (3*RB each), double buffered. Q: fp16 hi in regs.
// ---------------------------------------------------------------------------
#define RB 17408   // 64 rows * 272 B (stride 136 fp16)
#define A_SMEM (6u * RB)   // 104448

__global__ __launch_bounds__(256) void attn_mma(
    const __half* __restrict__ q_, const __half* __restrict__ kh_,
    const __half* __restrict__ kl_, const __half* __restrict__ vh_,
    __half* __restrict__ chi, __half* __restrict__ clo)
{
    extern __shared__ char smem[];
    const uint32_t sbase = (uint32_t)__cvta_generic_to_shared(smem);

    const int tid = threadIdx.x, lane = tid & 31, w = tid >> 5;
    const int q0 = blockIdx.x * 128;
    const int h  = blockIdx.y, b = blockIdx.z;
    const int kvh = h >> 2;
    const float scl = 0.08838834764831845f;

    // stage Q hi (128 rows x 256B)
    {
        int r = tid >> 1;
        size_t gbase = ((size_t)(b * S_ + q0 + r)) * (H_ * D_) + h * D_;
        const uint4* gq = (const uint4*)(q_ + gbase);
        #pragma unroll
        for (int u = 0; u < 8; u++) {
            int c = (tid & 1) * 8 + u;
            *(uint4*)(smem + (size_t)r * 272 + c * 16) = gq[c];
        }
    }
    __syncthreads();

    uint32_t ah[8][4];
    {
        uint32_t qro = (uint32_t)((w * 16 + (lane & 15)) * 272);
        #pragma unroll
        for (int d = 0; d < 8; d++) {
            uint32_t co = (uint32_t)((d * 16 + (lane >> 4) * 8) * 2);
            LDSM4(ah[d], sbase + qro + co);
        }
    }
    __syncthreads();

    float pacc[16][4];
    #pragma unroll
    for (int g = 0; g < 16; g++)
        #pragma unroll
        for (int r = 0; r < 4; r++) pacc[g][r] = 0.f;

    float m_run0 = -1e30f, m_run1 = -1e30f, l0 = 0.f, l1 = 0.f;

    const int ibase = q0 + w * 16;
    const int i0 = ibase + (lane >> 2);
    const int i1 = i0 + 8;

    int t0 = q0 - 1024; if (t0 < 0) t0 = 0;
    const int n = (q0 + 128 - t0) >> 6;

    const int crow = tid >> 2;
    const size_t grow = ((size_t)b * S_) * (KV_ * D_) + (size_t)kvh * D_;

    {
        size_t gb = grow + (size_t)(t0 + crow) * (KV_ * D_);
        #pragma unroll
        for (int u = 0; u < 4; u++) {
            int c = (tid & 3) * 4 + u;
            uint32_t so = (uint32_t)(crow * 272 + c * 16);
            CP16(sbase + so,          kh_ + gb + c * 8);
            CP16(sbase + RB + so,     kl_ + gb + c * 8);
            CP16(sbase + 2 * RB + so, vh_ + gb + c * 8);
        }
        CP_COMMIT();
    }

    for (int it = 0; it < n; it++) {
        const int t = t0 + it * 64;
        if (it + 1 < n) {
            uint32_t st = (uint32_t)((it + 1) & 1) * 3 * RB;
            size_t gb = grow + (size_t)(t + 64 + crow) * (KV_ * D_);
            #pragma unroll
            for (int u = 0; u < 4; u++) {
                int c = (tid & 3) * 4 + u;
                uint32_t so = st + (uint32_t)(crow * 272 + c * 16);
                CP16(sbase + so,          kh_ + gb + c * 8);
                CP16(sbase + RB + so,     kl_ + gb + c * 8);
                CP16(sbase + 2 * RB + so, vh_ + gb + c * 8);
            }
            CP_COMMIT();
            CP_WAIT1();
        } else {
            CP_WAIT0();
        }
        __syncthreads();

        const uint32_t khb = sbase + (uint32_t)(it & 1) * 3 * RB;
        const uint32_t klb = khb + RB;
        const uint32_t vhb = khb + 2 * RB;

        float sacc[8][4];
        #pragma unroll
        for (int g = 0; g < 8; g++)
            #pragma unroll
            for (int r = 0; r < 4; r++) sacc[g][r] = 0.f;

        #pragma unroll
        for (int d = 0; d < 8; d++) {
            uint32_t co = (uint32_t)((d * 16 + ((lane >> 3) & 1) * 8) * 2);
            #pragma unroll
            for (int g = 0; g < 4; g++) {
                uint32_t ro = (uint32_t)((g * 16 + ((lane >> 4) << 3) + (lane & 7)) * 272);
                uint32_t k4h[4], k4l[4];
                LDSM4(k4h, khb + ro + co);
                LDSM4(k4l, klb + ro + co);
                MMAF16(sacc[2 * g],     ah[d], k4h[0], k4h[1]);
                MMAF16(sacc[2 * g],     ah[d], k4l[0], k4l[1]);
                MMAF16(sacc[2 * g + 1], ah[d], k4h[2], k4h[3]);
                MMAF16(sacc[2 * g + 1], ah[d], k4l[2], k4l[3]);
            }
        }

        const bool need_mask = (t + 63 >= ibase) || (t + 1009 <= ibase);
        float m0 = -INFINITY, m1 = -INFINITY;
        #pragma unroll
        for (int g = 0; g < 8; g++) {
            int jb = t + g * 8 + 2 * (lane & 3);
            float s0 = sacc[g][0] * scl, s1 = sacc[g][1] * scl;
            float s2 = sacc[g][2] * scl, s3 = sacc[g][3] * scl;
            if (need_mask) {
                s0 = ((jb     <= i0) && (i0 - jb < 1024))     ? s0 : -INFINITY;
                s1 = ((jb + 1 <= i0) && (i0 - jb - 1 < 1024)) ? s1 : -INFINITY;
                s2 = ((jb     <= i1) && (i1 - jb < 1024))     ? s2 : -INFINITY;
                s3 = ((jb + 1 <= i1) && (i1 - jb - 1 < 1024)) ? s3 : -INFINITY;
            }
            sacc[g][0] = s0; sacc[g][1] = s1; sacc[g][2] = s2; sacc[g][3] = s3;
            m0 = fmaxf(m0, fmaxf(s0, s1));
            m1 = fmaxf(m1, fmaxf(s2, s3));
        }
        m0 = fmaxf(m0, __shfl_xor_sync(0xffffffffu, m0, 1));
        m0 = fmaxf(m0, __shfl_xor_sync(0xffffffffu, m0, 2));
        m1 = fmaxf(m1, __shfl_xor_sync(0xffffffffu, m1, 1));
        m1 = fmaxf(m1, __shfl_xor_sync(0xffffffffu, m1, 2));

        float mn0 = fmaxf(m_run0, m0), mn1 = fmaxf(m_run1, m1);
        float a0 = __expf(m_run0 - mn0), a1 = __expf(m_run1 - mn1);
        m_run0 = mn0; m_run1 = mn1;

        float rs0 = 0.f, rs1 = 0.f;
        #pragma unroll
        for (int g = 0; g < 8; g++) {
            float p0 = __expf(sacc[g][0] - mn0);
            float p1 = __expf(sacc[g][1] - mn0);
            float p2 = __expf(sacc[g][2] - mn1);
            float p3 = __expf(sacc[g][3] - mn1);
            sacc[g][0] = p0; sacc[g][1] = p1; sacc[g][2] = p2; sacc[g][3] = p3;
            rs0 += p0 + p1; rs1 += p2 + p3;
        }
        rs0 += __shfl_xor_sync(0xffffffffu, rs0, 1);
        rs0 += __shfl_xor_sync(0xffffffffu, rs0, 2);
        rs1 += __shfl_xor_sync(0xffffffffu, rs1, 1);
        rs1 += __shfl_xor_sync(0xffffffffu, rs1, 2);
        l0 = l0 * a0 + rs0;
        l1 = l1 * a1 + rs1;

        #pragma unroll
        for (int g = 0; g < 16; g++) {
            pacc[g][0] *= a0; pacc[g][1] *= a0;
            pacc[g][2] *= a1; pacc[g][3] *= a1;
        }

        // P hi/lo (fp16) A-fragments
        uint32_t ph[4][4], pl[4][4];
        #pragma unroll
        for (int kt = 0; kt < 4; kt++) {
            #pragma unroll
            for (int qq = 0; qq < 2; qq++) {
                #pragma unroll
                for (int r2 = 0; r2 < 2; r2++) {
                    float x0 = sacc[2 * kt + qq][r2 * 2];
                    float x1 = sacc[2 * kt + qq][r2 * 2 + 1];
                    __half2 hh = __floats2half2_rn(x0, x1);
                    __half2 ll = __floats2half2_rn(
                        x0 - __half2float(hh.x), x1 - __half2float(hh.y));
                    ph[kt][qq * 2 + r2] = *(uint32_t*)&hh;
                    pl[kt][qq * 2 + r2] = *(uint32_t*)&ll;
                }
            }
        }

        #pragma unroll
        for (int kt = 0; kt < 4; kt++) {
            uint32_t ro = (uint32_t)((kt * 16 + (lane & 15)) * 272);
            uint32_t co = (uint32_t)(((lane >> 4) * 8) * 2);
            #pragma unroll
            for (int g = 0; g < 8; g++) {
                uint32_t v4h[4];
                LDSM4T(v4h, vhb + ro + co + g * 32);
                MMAF16(pacc[2 * g],     ph[kt], v4h[0], v4h[1]);
                MMAF16(pacc[2 * g],     pl[kt], v4h[0], v4h[1]);
                MMAF16(pacc[2 * g + 1], ph[kt], v4h[2], v4h[3]);
                MMAF16(pacc[2 * g + 1], pl[kt], v4h[2], v4h[3]);
            }
        }
        __syncthreads();
    }

    float inv0 = 1.f / l0, inv1 = 1.f / l1;
    size_t base0 = ((size_t)(b * S_ + i0)) * (H_ * D_) + h * D_;
    size_t base1 = base0 + (size_t)8 * (H_ * D_);
    #pragma unroll
    for (int g = 0; g < 16; g++) {
        int col = g * 8 + 2 * (lane & 3);
        float o0 = pacc[g][0] * inv0, o1 = pacc[g][1] * inv0;
        float o2 = pacc[g][2] * inv1, o3 = pacc[g][3] * inv1;
        __half2 h0 = __floats2half2_rn(o0, o1);
        __half2 l0v = __floats2half2_rn(
            o0 - __half2float(h0.x), o1 - __half2float(h0.y));
        __half2 h1 = __floats2half2_rn(o2, o3);
        __half2 l1v = __floats2half2_rn(
            o2 - __half2float(h1.x), o3 - __half2float(h1.y));
        *(uint32_t*)&chi[base0 + col] = *(uint32_t*)&h0;
        *(uint32_t*)&clo[base0 + col] = *(uint32_t*)&l0v;
        *(uint32_t*)&chi[base1 + col] = *(uint32_t*)&h1;
        *(uint32_t*)&clo[base1 + col] = *(uint32_t*)&l1v;
    }
}

// ---------------------------------------------------------------------------
extern "C" void kernel_launch(void* const* d_in, const int* in_sizes, int n_in,
                              void* d_out, int out_size)
{
    const float* x    = (const float*)d_in[0];
    const float* cosp = (const float*)d_in[1];
    const float* sinp = (const float*)d_in[2];
    const float* Wq   = (const float*)d_in[3];
    const float* Wk   = (const float*)d_in[4];
    const float* Wv   = (const float*)d_in[5];
    const float* Wo   = (const float*)d_in[6];
    float* out = (float*)d_out;

    __half *xhi, *xlo, *wqhi, *wqlo, *wkhi, *wklo, *wvhi, *wvlo, *wohi, *wolo;
    __half *chi, *clo, *qh, *kh, *kl, *vh;
    cudaGetSymbolAddress((void**)&xhi, g_xhi);
    cudaGetSymbolAddress((void**)&xlo, g_xlo);
    cudaGetSymbolAddress((void**)&wqhi, g_wqhi);
    cudaGetSymbolAddress((void**)&wqlo, g_wqlo);
    cudaGetSymbolAddress((void**)&wkhi, g_wkhi);
    cudaGetSymbolAddress((void**)&wklo, g_wklo);
    cudaGetSymbolAddress((void**)&wvhi, g_wvhi);
    cudaGetSymbolAddress((void**)&wvlo, g_wvlo);
    cudaGetSymbolAddress((void**)&wohi, g_wohi);
    cudaGetSymbolAddress((void**)&wolo, g_wolo);
    cudaGetSymbolAddress((void**)&chi, g_chi);
    cudaGetSymbolAddress((void**)&clo, g_clo);
    cudaGetSymbolAddress((void**)&qh, g_qh);
    cudaGetSymbolAddress((void**)&kh, g_kh);
    cudaGetSymbolAddress((void**)&kl, g_kl);
    cudaGetSymbolAddress((void**)&vh, g_vh);

    static bool attr_done = false;
    if (!attr_done) {
        cudaFuncSetAttribute(attn_mma,
            cudaFuncAttributeMaxDynamicSharedMemorySize, A_SMEM);
        cudaFuncSetAttribute(gemm_qkv,
            cudaFuncAttributeMaxDynamicSharedMemorySize, G_SMEM);
        cudaFuncSetAttribute(gemm_one,
            cudaFuncAttributeMaxDynamicSharedMemorySize, G_SMEM);
        attr_done = true;
    }

    const int M = B_ * S_;

    // one fused split launch (fp16 hi/lo)
    {
        size_t blocks = (N2_ALL + 255) / 256;
        split_all<<<(unsigned)blocks, 256>>>(
            (const float2*)x, (const float2*)Wq, (const float2*)Wk,
            (const float2*)Wv, (const float2*)Wo,
            (__half2*)xhi,  (__half2*)xlo,
            (__half2*)wqhi, (__half2*)wqlo,
            (__half2*)wkhi, (__half2*)wklo,
            (__half2*)wvhi, (__half2*)wvlo,
            (__half2*)wohi, (__half2*)wolo);
    }

    // fused Q/K/V projections + rope/rms epilogue
    gemm_qkv<<<dim3(24, M / 128), 256, G_SMEM>>>(
        xhi, wqhi, wqlo, wkhi, wklo, wvhi, wvlo,
        qh, kh, kl, vh, cosp, sinp);

    // attention (fp16 2-pass)
    attn_mma<<<dim3(S_ / 128, H_, B_), 256, A_SMEM>>>(
        qh, kh, kl, vh, chi, clo);

    // output projection (fp16 2-pass)
    gemm_one<<<dim3(E_ / 128, M / 128), 256, G_SMEM>>>(
        chi, wohi, wolo, out, E_, E_);
}

// round 11
// speedup vs baseline: 1.7902x; 1.0124x over previous
#include <cuda_runtime.h>
#include <cuda_bf16.h>
#include <cuda_fp16.h>
#include <math.h>
#include <stdint.h>

#define B_  2
#define S_  2048
#define E_  2048
#define H_  16
#define KV_ 4
#define D_  128
#define WIN_ 1024

// fp16 hi/lo scratch (GEMM operands)
__device__ __half g_xhi[(size_t)B_ * S_ * E_];
__device__ __half g_xlo[(size_t)B_ * S_ * E_];
__device__ __half g_wqhi[(size_t)H_ * D_ * E_];
__device__ __half g_wqlo[(size_t)H_ * D_ * E_];
__device__ __half g_wkhi[(size_t)KV_ * D_ * E_];
__device__ __half g_wklo[(size_t)KV_ * D_ * E_];
__device__ __half g_wvhi[(size_t)KV_ * D_ * E_];
__device__ __half g_wvlo[(size_t)KV_ * D_ * E_];
__device__ __half g_wohi[(size_t)E_ * H_ * D_];
__device__ __half g_wolo[(size_t)E_ * H_ * D_];
__device__ __half g_chi[(size_t)B_ * S_ * H_ * D_];
__device__ __half g_clo[(size_t)B_ * S_ * H_ * D_];

// fp16 attention operands
__device__ __half g_qh[(size_t)B_ * S_ * H_ * D_];
__device__ __half g_kh[(size_t)B_ * S_ * KV_ * D_];
__device__ __half g_kl[(size_t)B_ * S_ * KV_ * D_];
__device__ __half g_vh[(size_t)B_ * S_ * KV_ * D_];

// Q pre-scale: D^-0.5 * log2(e)  (softmax done in base-2)
#define QSCALE 0.12752820723310574f

// ---------------------------------------------------------------------------
// Fused fp16 hi/lo splitter, 4 float2 per thread (MLP=4).
// All segment boundaries are multiples of 4, so a group never straddles.
// ---------------------------------------------------------------------------
#define N2_X  ((size_t)B_ * S_ * E_ / 2)
#define N2_WQ ((size_t)H_ * D_ * E_ / 2)
#define N2_WK ((size_t)KV_ * D_ * E_ / 2)
#define N2_ALL (N2_X + 2 * N2_WQ + 2 * N2_WK)

__global__ __launch_bounds__(256) void split_all(
    const float2* __restrict__ x,  const float2* __restrict__ wq,
    const float2* __restrict__ wk, const float2* __restrict__ wv,
    const float2* __restrict__ wo,
    __half2* __restrict__ xhi,  __half2* __restrict__ xlo,
    __half2* __restrict__ qhi,  __half2* __restrict__ qlo,
    __half2* __restrict__ khi,  __half2* __restrict__ klo,
    __half2* __restrict__ vhi,  __half2* __restrict__ vlo,
    __half2* __restrict__ ohi,  __half2* __restrict__ olo)
{
    size_t g = ((size_t)blockIdx.x * blockDim.x + threadIdx.x) * 4;
    if (g >= N2_ALL) return;

    const float2* src;
    __half2 *dh, *dl;
    size_t off = g;
    if (off < N2_X)                    { src = x;  dh = xhi; dl = xlo; }
    else if ((off -= N2_X) < N2_WQ)    { src = wq; dh = qhi; dl = qlo; }
    else if ((off -= N2_WQ) < N2_WK)   { src = wk; dh = khi; dl = klo; }
    else if ((off -= N2_WK) < N2_WK)   { src = wv; dh = vhi; dl = vlo; }
    else { off -= N2_WK;                 src = wo; dh = ohi; dl = olo; }

    float2 v0 = src[off], v1 = src[off + 1], v2 = src[off + 2], v3 = src[off + 3];
    float2 vv[4] = {v0, v1, v2, v3};
    #pragma unroll
    for (int u = 0; u < 4; u++) {
        __half h0 = __float2half(vv[u].x);
        __half h1 = __float2half(vv[u].y);
        __half2 hh; hh.x = h0; hh.y = h1;
        __half2 ll;
        ll.x = __float2half(vv[u].x - __half2float(h0));
        ll.y = __float2half(vv[u].y - __half2float(h1));
        dh[off + u] = hh;
        dl[off + u] = ll;
    }
}

// ---------------------------------------------------------------------------
// PTX helpers
// ---------------------------------------------------------------------------
#define CP16(dst, src) \
    asm volatile("cp.async.cg.shared.global [%0], [%1], 16;\n" :: "r"(dst), "l"(src))
#define CP_COMMIT() asm volatile("cp.async.commit_group;\n" ::)
#define CP_WAIT2()  asm volatile("cp.async.wait_group 2;\n" ::)
#define CP_WAIT1()  asm volatile("cp.async.wait_group 1;\n" ::)
#define CP_WAIT0()  asm volatile("cp.async.wait_group 0;\n" ::)

#define LDSM4(R, addr) \
    asm volatile("ldmatrix.sync.aligned.m8n8.x4.shared.b16 {%0,%1,%2,%3}, [%4];\n" \
        : "=r"(R[0]), "=r"(R[1]), "=r"(R[2]), "=r"(R[3]) : "r"(addr))
#define LDSM4T(R, addr) \
    asm volatile("ldmatrix.sync.aligned.m8n8.x4.trans.shared.b16 {%0,%1,%2,%3}, [%4];\n" \
        : "=r"(R[0]), "=r"(R[1]), "=r"(R[2]), "=r"(R[3]) : "r"(addr))

#define MMAF16(acc, a, b0, b1) \
    asm volatile("mma.sync.aligned.m16n8k16.row.col.f32.f16.f16.f32 " \
        "{%0,%1,%2,%3}, {%4,%5,%6,%7}, {%8,%9}, {%0,%1,%2,%3};\n" \
        : "+f"(acc[0]), "+f"(acc[1]), "+f"(acc[2]), "+f"(acc[3]) \
        : "r"(a[0]), "r"(a[1]), "r"(a[2]), "r"(a[3]), "r"(b0), "r"(b1))

__device__ __forceinline__ float ex2f(float x) {
    float r;
    asm("ex2.approx.f32 %0, %1;" : "=f"(r) : "f"(x));
    return r;
}

// ---------------------------------------------------------------------------
// GEMM core (fp16 2-pass): C = Ah@Bh^T + Ah@Bl^T   (fp32 accum)
// R9-proven: 4-stage cp.async pipeline, 1 barrier/K16, 2 CTAs/SM.
// mode 0: fp32 out. mode 1: fp16 hi out. mode 2: rope+rms*oscale -> fp16.
// ---------------------------------------------------------------------------
#define SSTR   24
#define TILE_B (128u * SSTR * 2u)       // 6144 B
#define STG_B  (3u * TILE_B)            // Ah|Bh|Bl = 18432 B
#define G_SMEM (4u * STG_B)             // 73728 B

__device__ __forceinline__ void gemm_core(
    const __half* __restrict__ Ah,
    const __half* __restrict__ Bh, const __half* __restrict__ Bl,
    float* __restrict__ C,
    __half* __restrict__ Chh, __half* __restrict__ Chl,
    int N, int K, int bm, int bn, char* smem, int mode,
    const float* __restrict__ cs, const float* __restrict__ sn, float oscale)
{
    const uint32_t sb = (uint32_t)__cvta_generic_to_shared(smem);
    const int tid = threadIdx.x;
    const int lane = tid & 31;
    const int wid = tid >> 5;
    const int wm = wid & 1;
    const int wn = wid >> 1;

    const int lrow = tid >> 1;
    const int lkc  = tid & 1;
    const __half* gah = Ah + (size_t)(bm * 128 + lrow) * K + lkc * 8;
    const __half* gbh = Bh + (size_t)(bn * 128 + lrow) * K + lkc * 8;
    const __half* gbl = Bl + (size_t)(bn * 128 + lrow) * K + lkc * 8;
    const uint32_t sOff = (uint32_t)(lrow * SSTR + lkc * 8) * 2;

    const uint32_t aLn = (uint32_t)((wm * 64 + (lane & 15)) * SSTR + (lane >> 4) * 8) * 2;
    const uint32_t bLn = (uint32_t)((wn * 32 + ((lane >> 4) << 3) + (lane & 7)) * SSTR
                                    + ((lane >> 3) & 1) * 8) * 2;

    float acc[4][4][4];
    #pragma unroll
    for (int i = 0; i < 4; i++)
        #pragma unroll
        for (int j = 0; j < 4; j++)
            #pragma unroll
            for (int r = 0; r < 4; r++) acc[i][j][r] = 0.f;

    const int T = K / 16;

    auto stage_load = [&](uint32_t st, int kt) {
        uint32_t base = sb + st * STG_B + sOff;
        CP16(base,              gah + kt * 16);
        CP16(base + TILE_B,     gbh + kt * 16);
        CP16(base + 2 * TILE_B, gbl + kt * 16);
        CP_COMMIT();
    };

    stage_load(0, 0);
    stage_load(1, 1);
    stage_load(2, 2);

    for (int t = 0; t < T; t++) {
        CP_WAIT2();
        __syncthreads();

        const uint32_t ab = sb + (uint32_t)(t & 3) * STG_B;
        const uint32_t bb = ab + TILE_B;

        uint32_t ah[4][4], bh[2][4], bl[2][4];
        #pragma unroll
        for (int mt = 0; mt < 4; mt++)
            LDSM4(ah[mt], ab + aLn + mt * (16 * SSTR * 2));
        #pragma unroll
        for (int pr = 0; pr < 2; pr++) {
            LDSM4(bh[pr], bb + bLn + pr * (16 * SSTR * 2));
            LDSM4(bl[pr], bb + TILE_B + bLn + pr * (16 * SSTR * 2));
        }

        if (t + 3 < T) stage_load((uint32_t)((t + 3) & 3), t + 3);
        else           CP_COMMIT();

        #pragma unroll
        for (int mt = 0; mt < 4; mt++)
            #pragma unroll
            for (int nt = 0; nt < 4; nt++) {
                const int pr = nt >> 1, q = (nt & 1) * 2;
                MMAF16(acc[mt][nt], ah[mt], bh[pr][q], bh[pr][q + 1]);
            }
        #pragma unroll
        for (int mt = 0; mt < 4; mt++)
            #pragma unroll
            for (int nt = 0; nt < 4; nt++) {
                const int pr = nt >> 1, q = (nt & 1) * 2;
                MMAF16(acc[mt][nt], ah[mt], bl[pr][q], bl[pr][q + 1]);
            }
    }

    if (mode == 0) {
        #pragma unroll
        for (int mt = 0; mt < 4; mt++) {
            const int r0 = bm * 128 + wm * 64 + mt * 16 + (lane >> 2);
            #pragma unroll
            for (int nt = 0; nt < 4; nt++) {
                const int c0 = bn * 128 + wn * 32 + nt * 8 + (lane & 3) * 2;
                *(float2*)&C[(size_t)r0 * N + c0] =
                    make_float2(acc[mt][nt][0], acc[mt][nt][1]);
                *(float2*)&C[(size_t)(r0 + 8) * N + c0] =
                    make_float2(acc[mt][nt][2], acc[mt][nt][3]);
            }
        }
    } else if (mode == 1) {
        #pragma unroll
        for (int mt = 0; mt < 4; mt++) {
            const int r0 = bm * 128 + wm * 64 + mt * 16 + (lane >> 2);
            #pragma unroll
            for (int nt = 0; nt < 4; nt++) {
                const int c0 = bn * 128 + wn * 32 + nt * 8 + (lane & 3) * 2;
                #pragma unroll
                for (int hf = 0; hf < 2; hf++) {
                    __half2 hh = __floats2half2_rn(acc[mt][nt][hf * 2],
                                                   acc[mt][nt][hf * 2 + 1]);
                    *(uint32_t*)&Chh[(size_t)(r0 + hf * 8) * N + c0] =
                        *(uint32_t*)&hh;
                }
            }
        }
    } else {
        // mode 2: rope + rmsnorm (+oscale) fused epilogue -> fp16 hi (+lo)
        CP_WAIT0();
        __syncthreads();
        float* st = (float*)smem;
        #pragma unroll
        for (int mt = 0; mt < 4; mt++) {
            const int r0 = wm * 64 + mt * 16 + (lane >> 2);
            #pragma unroll
            for (int nt = 0; nt < 4; nt++) {
                const int c0 = wn * 32 + nt * 8 + (lane & 3) * 2;
                *(float2*)&st[r0 * 132 + c0] =
                    make_float2(acc[mt][nt][0], acc[mt][nt][1]);
                *(float2*)&st[(r0 + 8) * 132 + c0] =
                    make_float2(acc[mt][nt][2], acc[mt][nt][3]);
            }
        }
        __syncthreads();

        const int cb = bn * 128;
        for (int rr = 0; rr < 16; rr++) {
            int r = wid * 16 + rr;
            int grow_ = bm * 128 + r;
            int s = grow_ & (S_ - 1);
            float x1a = st[r * 132 + lane],      x1b = st[r * 132 + lane + 32];
            float x2a = st[r * 132 + lane + 64], x2b = st[r * 132 + lane + 96];
            float ca = cs[s * 64 + lane], cbv = cs[s * 64 + lane + 32];
            float sa = sn[s * 64 + lane], sbv = sn[s * 64 + lane + 32];

            float o1a =  x1a * ca  + x2a * sa;
            float o1b =  x1b * cbv + x2b * sbv;
            float o2a = -x1a * sa  + x2a * ca;
            float o2b = -x1b * sbv + x2b * cbv;

            float ss = o1a * o1a + o1b * o1b + o2a * o2a + o2b * o2b;
            #pragma unroll
            for (int o = 16; o; o >>= 1) ss += __shfl_xor_sync(0xffffffffu, ss, o);
            float scale = rsqrtf(ss * (1.f / 128.f) + 1.1920928955078125e-07f)
                        * oscale;

            float v4[4] = {o1a * scale, o1b * scale, o2a * scale, o2b * scale};
            size_t gb = (size_t)grow_ * N + cb + lane;
            #pragma unroll
            for (int u = 0; u < 4; u++) {
                __half hh = __float2half(v4[u]);
                Chh[gb + u * 32] = hh;
                if (Chl) Chl[gb + u * 32] =
                    __float2half(v4[u] - __half2float(hh));
            }
        }
    }
}

// Fused Q/K/V projection + rope/rms epilogue (Q: hi scaled, K: hi+lo); V: hi.
__global__ __launch_bounds__(256, 2) void gemm_qkv(
    const __half* __restrict__ xh,
    const __half* __restrict__ wqh, const __half* __restrict__ wql,
    const __half* __restrict__ wkh, const __half* __restrict__ wkl,
    const __half* __restrict__ wvh, const __half* __restrict__ wvl,
    __half* __restrict__ qh, __half* __restrict__ kh, __half* __restrict__ kl,
    __half* __restrict__ vh,
    const float* __restrict__ cosp, const float* __restrict__ sinp)
{
    extern __shared__ char smem[];
    const int bx = blockIdx.x;
    if (bx < 16) {
        gemm_core(xh, wqh, wql, nullptr, qh, nullptr,
                  H_ * D_, E_, blockIdx.y, bx, smem, 2, cosp, sinp, QSCALE);
    } else if (bx < 20) {
        gemm_core(xh, wkh, wkl, nullptr, kh, kl,
                  KV_ * D_, E_, blockIdx.y, bx - 16, smem, 2, cosp, sinp, 1.f);
    } else {
        gemm_core(xh, wvh, wvl, nullptr, vh, nullptr,
                  KV_ * D_, E_, blockIdx.y, bx - 20, smem, 1, nullptr, nullptr, 1.f);
    }
}

__global__ __launch_bounds__(256, 2) void gemm_one(
    const __half* __restrict__ Ah,
    const __half* __restrict__ Bh, const __half* __restrict__ Bl,
    float* __restrict__ C, int N, int K)
{
    extern __shared__ char smem[];
    gemm_core(Ah, Bh, Bl, C, nullptr, nullptr, N, K,
              blockIdx.y, blockIdx.x, smem, 0, nullptr, nullptr, 1.f);
}

// ---------------------------------------------------------------------------
// fp16 2-pass sliding-window flash attention; softmax in base-2
// (Q pre-scaled by D^-0.5 * log2 e).
// ---------------------------------------------------------------------------
#define RB 17408   // 64 rows * 272 B (stride 136 fp16)
#define A_SMEM (6u * RB)

__global__ __launch_bounds__(256) void attn_mma(
    const __half* __restrict__ q_, const __half* __restrict__ kh_,
    const __half* __restrict__ kl_, const __half* __restrict__ vh_,
    __half* __restrict__ chi, __half* __restrict__ clo)
{
    extern __shared__ char smem[];
    const uint32_t sbase = (uint32_t)__cvta_generic_to_shared(smem);

    const int tid = threadIdx.x, lane = tid & 31, w = tid >> 5;
    const int q0 = blockIdx.x * 128;
    const int h  = blockIdx.y, b = blockIdx.z;
    const int kvh = h >> 2;

    {
        int r = tid >> 1;
        size_t gbase = ((size_t)(b * S_ + q0 + r)) * (H_ * D_) + h * D_;
        const uint4* gq = (const uint4*)(q_ + gbase);
        #pragma unroll
        for (int u = 0; u < 8; u++) {
            int c = (tid & 1) * 8 + u;
            *(uint4*)(smem + (size_t)r * 272 + c * 16) = gq[c];
        }
    }
    __syncthreads();

    uint32_t ah[8][4];
    {
        uint32_t qro = (uint32_t)((w * 16 + (lane & 15)) * 272);
        #pragma unroll
        for (int d = 0; d < 8; d++) {
            uint32_t co = (uint32_t)((d * 16 + (lane >> 4) * 8) * 2);
            LDSM4(ah[d], sbase + qro + co);
        }
    }
    __syncthreads();

    float pacc[16][4];
    #pragma unroll
    for (int g = 0; g < 16; g++)
        #pragma unroll
        for (int r = 0; r < 4; r++) pacc[g][r] = 0.f;

    float m_run0 = -1e30f, m_run1 = -1e30f, l0 = 0.f, l1 = 0.f;

    const int ibase = q0 + w * 16;
    const int i0 = ibase + (lane >> 2);
    const int i1 = i0 + 8;

    int t0 = q0 - 1024; if (t0 < 0) t0 = 0;
    const int n = (q0 + 128 - t0) >> 6;

    const int crow = tid >> 2;
    const size_t grow = ((size_t)b * S_) * (KV_ * D_) + (size_t)kvh * D_;

    {
        size_t gb = grow + (size_t)(t0 + crow) * (KV_ * D_);
        #pragma unroll
        for (int u = 0; u < 4; u++) {
            int c = (tid & 3) * 4 + u;
            uint32_t so = (uint32_t)(crow * 272 + c * 16);
            CP16(sbase + so,          kh_ + gb + c * 8);
            CP16(sbase + RB + so,     kl_ + gb + c * 8);
            CP16(sbase + 2 * RB + so, vh_ + gb + c * 8);
        }
        CP_COMMIT();
    }

    for (int it = 0; it < n; it++) {
        const int t = t0 + it * 64;
        if (it + 1 < n) {
            uint32_t st = (uint32_t)((it + 1) & 1) * 3 * RB;
            size_t gb = grow + (size_t)(t + 64 + crow) * (KV_ * D_);
            #pragma unroll
            for (int u = 0; u < 4; u++) {
                int c = (tid & 3) * 4 + u;
                uint32_t so = st + (uint32_t)(crow * 272 + c * 16);
                CP16(sbase + so,          kh_ + gb + c * 8);
                CP16(sbase + RB + so,     kl_ + gb + c * 8);
                CP16(sbase + 2 * RB + so, vh_ + gb + c * 8);
            }
            CP_COMMIT();
            CP_WAIT1();
        } else {
            CP_WAIT0();
        }
        __syncthreads();

        const uint32_t khb = sbase + (uint32_t)(it & 1) * 3 * RB;
        const uint32_t klb = khb + RB;
        const uint32_t vhb = khb + 2 * RB;

        float sacc[8][4];
        #pragma unroll
        for (int g = 0; g < 8; g++)
            #pragma unroll
            for (int r = 0; r < 4; r++) sacc[g][r] = 0.f;

        #pragma unroll
        for (int d = 0; d < 8; d++) {
            uint32_t co = (uint32_t)((d * 16 + ((lane >> 3) & 1) * 8) * 2);
            #pragma unroll
            for (int g = 0; g < 4; g++) {
                uint32_t ro = (uint32_t)((g * 16 + ((lane >> 4) << 3) + (lane & 7)) * 272);
                uint32_t k4h[4], k4l[4];
                LDSM4(k4h, khb + ro + co);
                LDSM4(k4l, klb + ro + co);
                MMAF16(sacc[2 * g],     ah[d], k4h[0], k4h[1]);
                MMAF16(sacc[2 * g],     ah[d], k4l[0], k4l[1]);
                MMAF16(sacc[2 * g + 1], ah[d], k4h[2], k4h[3]);
                MMAF16(sacc[2 * g + 1], ah[d], k4l[2], k4l[3]);
            }
        }

        const bool need_mask = (t + 63 >= ibase) || (t + 1009 <= ibase);
        float m0 = -INFINITY, m1 = -INFINITY;
        #pragma unroll
        for (int g = 0; g < 8; g++) {
            float s0 = sacc[g][0], s1 = sacc[g][1];
            float s2 = sacc[g][2], s3 = sacc[g][3];
            if (need_mask) {
                int jb = t + g * 8 + 2 * (lane & 3);
                s0 = ((jb     <= i0) && (i0 - jb < 1024))     ? s0 : -INFINITY;
                s1 = ((jb + 1 <= i0) && (i0 - jb - 1 < 1024)) ? s1 : -INFINITY;
                s2 = ((jb     <= i1) && (i1 - jb < 1024))     ? s2 : -INFINITY;
                s3 = ((jb + 1 <= i1) && (i1 - jb - 1 < 1024)) ? s3 : -INFINITY;
                sacc[g][0] = s0; sacc[g][1] = s1;
                sacc[g][2] = s2; sacc[g][3] = s3;
            }
            m0 = fmaxf(m0, fmaxf(s0, s1));
            m1 = fmaxf(m1, fmaxf(s2, s3));
        }
        m0 = fmaxf(m0, __shfl_xor_sync(0xffffffffu, m0, 1));
        m0 = fmaxf(m0, __shfl_xor_sync(0xffffffffu, m0, 2));
        m1 = fmaxf(m1, __shfl_xor_sync(0xffffffffu, m1, 1));
        m1 = fmaxf(m1, __shfl_xor_sync(0xffffffffu, m1, 2));

        float mn0 = fmaxf(m_run0, m0), mn1 = fmaxf(m_run1, m1);
        float a0 = ex2f(m_run0 - mn0), a1 = ex2f(m_run1 - mn1);
        m_run0 = mn0; m_run1 = mn1;

        float rs0 = 0.f, rs1 = 0.f;
        #pragma unroll
        for (int g = 0; g < 8; g++) {
            float p0 = ex2f(sacc[g][0] - mn0);
            float p1 = ex2f(sacc[g][1] - mn0);
            float p2 = ex2f(sacc[g][2] - mn1);
            float p3 = ex2f(sacc[g][3] - mn1);
            sacc[g][0] = p0; sacc[g][1] = p1; sacc[g][2] = p2; sacc[g][3] = p3;
            rs0 += p0 + p1; rs1 += p2 + p3;
        }
        rs0 += __shfl_xor_sync(0xffffffffu, rs0, 1);
        rs0 += __shfl_xor_sync(0xffffffffu, rs0, 2);
        rs1 += __shfl_xor_sync(0xffffffffu, rs1, 1);
        rs1 += __shfl_xor_sync(0xffffffffu, rs1, 2);
        l0 = l0 * a0 + rs0;
        l1 = l1 * a1 + rs1;

        #pragma unroll
        for (int g = 0; g < 16; g++) {
            pacc[g][0] *= a0; pacc[g][1] *= a0;
            pacc[g][2] *= a1; pacc[g][3] *= a1;
        }

        uint32_t ph[4][4], pl[4][4];
        #pragma unroll
        for (int kt = 0; kt < 4; kt++) {
            #pragma unroll
            for (int qq = 0; qq < 2; qq++) {
                #pragma unroll
                for (int r2 = 0; r2 < 2; r2++) {
                    float x0 = sacc[2 * kt + qq][r2 * 2];
                    float x1 = sacc[2 * kt + qq][r2 * 2 + 1];
                    __half2 hh = __floats2half2_rn(x0, x1);
                    __half2 ll = __floats2half2_rn(
                        x0 - __half2float(hh.x), x1 - __half2float(hh.y));
                    ph[kt][qq * 2 + r2] = *(uint32_t*)&hh;
                    pl[kt][qq * 2 + r2] = *(uint32_t*)&ll;
                }
            }
        }

        #pragma unroll
        for (int kt = 0; kt < 4; kt++) {
            uint32_t ro = (uint32_t)((kt * 16 + (lane & 15)) * 272);
            uint32_t co = (uint32_t)(((lane >> 4) * 8) * 2);
            #pragma unroll
            for (int g = 0; g < 8; g++) {
                uint32_t v4h[4];
                LDSM4T(v4h, vhb + ro + co + g * 32);
                MMAF16(pacc[2 * g],     ph[kt], v4h[0], v4h[1]);
                MMAF16(pacc[2 * g],     pl[kt], v4h[0], v4h[1]);
                MMAF16(pacc[2 * g + 1], ph[kt], v4h[2], v4h[3]);
                MMAF16(pacc[2 * g + 1], pl[kt], v4h[2], v4h[3]);
            }
        }
        __syncthreads();
    }

    float inv0 = 1.f / l0, inv1 = 1.f / l1;
    size_t base0 = ((size_t)(b * S_ + i0)) * (H_ * D_) + h * D_;
    size_t base1 = base0 + (size_t)8 * (H_ * D_);
    #pragma unroll
    for (int g = 0; g < 16; g++) {
        int col = g * 8 + 2 * (lane & 3);
        float o0 = pacc[g][0] * inv0, o1 = pacc[g][1] * inv0;
        float o2 = pacc[g][2] * inv1, o3 = pacc[g][3] * inv1;
        __half2 h0 = __floats2half2_rn(o0, o1);
        __half2 l0v = __floats2half2_rn(
            o0 - __half2float(h0.x), o1 - __half2float(h0.y));
        __half2 h1 = __floats2half2_rn(o2, o3);
        __half2 l1v = __floats2half2_rn(
            o2 - __half2float(h1.x), o3 - __half2float(h1.y));
        *(uint32_t*)&chi[base0 + col] = *(uint32_t*)&h0;
        *(uint32_t*)&clo[base0 + col] = *(uint32_t*)&l0v;
        *(uint32_t*)&chi[base1 + col] = *(uint32_t*)&h1;
        *(uint32_t*)&clo[base1 + col] = *(uint32_t*)&l1v;
    }
}

// ---------------------------------------------------------------------------
extern "C" void kernel_launch(void* const* d_in, const int* in_sizes, int n_in,
                              void* d_out, int out_size)
{
    const float* x    = (const float*)d_in[0];
    const float* cosp = (const float*)d_in[1];
    const float* sinp = (const float*)d_in[2];
    const float* Wq   = (const float*)d_in[3];
    const float* Wk   = (const float*)d_in[4];
    const float* Wv   = (const float*)d_in[5];
    const float* Wo   = (const float*)d_in[6];
    float* out = (float*)d_out;

    __half *xhi, *xlo, *wqhi, *wqlo, *wkhi, *wklo, *wvhi, *wvlo, *wohi, *wolo;
    __half *chi, *clo, *qh, *kh, *kl, *vh;
    cudaGetSymbolAddress((void**)&xhi, g_xhi);
    cudaGetSymbolAddress((void**)&xlo, g_xlo);
    cudaGetSymbolAddress((void**)&wqhi, g_wqhi);
    cudaGetSymbolAddress((void**)&wqlo, g_wqlo);
    cudaGetSymbolAddress((void**)&wkhi, g_wkhi);
    cudaGetSymbolAddress((void**)&wklo, g_wklo);
    cudaGetSymbolAddress((void**)&wvhi, g_wvhi);
    cudaGetSymbolAddress((void**)&wvlo, g_wvlo);
    cudaGetSymbolAddress((void**)&wohi, g_wohi);
    cudaGetSymbolAddress((void**)&wolo, g_wolo);
    cudaGetSymbolAddress((void**)&chi, g_chi);
    cudaGetSymbolAddress((void**)&clo, g_clo);
    cudaGetSymbolAddress((void**)&qh, g_qh);
    cudaGetSymbolAddress((void**)&kh, g_kh);
    cudaGetSymbolAddress((void**)&kl, g_kl);
    cudaGetSymbolAddress((void**)&vh, g_vh);

    static bool attr_done = false;
    if (!attr_done) {
        cudaFuncSetAttribute(attn_mma,
            cudaFuncAttributeMaxDynamicSharedMemorySize, A_SMEM);
        cudaFuncSetAttribute(gemm_qkv,
            cudaFuncAttributeMaxDynamicSharedMemorySize, G_SMEM);
        cudaFuncSetAttribute(gemm_one,
            cudaFuncAttributeMaxDynamicSharedMemorySize, G_SMEM);
        attr_done = true;
    }

    const int M = B_ * S_;

    // fused split (4 float2 per thread)
    {
        size_t blocks = (N2_ALL / 4 + 255) / 256;
        split_all<<<(unsigned)blocks, 256>>>(
            (const float2*)x, (const float2*)Wq, (const float2*)Wk,
            (const float2*)Wv, (const float2*)Wo,
            (__half2*)xhi,  (__half2*)xlo,
            (__half2*)wqhi, (__half2*)wqlo,
            (__half2*)wkhi, (__half2*)wklo,
            (__half2*)wvhi, (__half2*)wvlo,
            (__half2*)wohi, (__half2*)wolo);
    }

    // fused Q/K/V projections + rope/rms epilogue (Q prescaled for base-2 softmax)
    gemm_qkv<<<dim3(24, M / 128), 256, G_SMEM>>>(
        xhi, wqhi, wqlo, wkhi, wklo, wvhi, wvlo,
        qh, kh, kl, vh, cosp, sinp);

    // attention
    attn_mma<<<dim3(S_ / 128, H_, B_), 256, A_SMEM>>>(
        qh, kh, kl, vh, chi, clo);

    // output projection
    gemm_one<<<dim3(E_ / 128, M / 128), 256, G_SMEM>>>(
        chi, wohi, wolo, out, E_, E_);
}